// round 4
// baseline (speedup 1.0000x reference)
#include <cuda_runtime.h>

#define NN   10000
#define FIN  512
#define ED   256
#define H0D  512
#define H1D  256
#define NE   160000
#define TT   (NE + NN)
#define TPAD ((TT + 63) & ~63)

// Scratch (device globals: no allocation allowed)
__device__ float g_A[NN * H0D];                     // emb @ W0[:256,:] + b0
__device__ float g_B[NN * H0D];                     // emb @ W0[256:,:]
__device__ float g_h[(size_t)TPAD * H1D];           // layer-2 activations per entry
__device__ unsigned long long g_seg[NN];            // per-node (lk_bits<<32 | idx) argmax
__device__ int g_owner[NN];                         // per-target winning source node

__device__ __forceinline__ unsigned int fenc(float f) {
    unsigned int u = __float_as_uint(f);
    return (u & 0x80000000u) ? ~u : (u | 0x80000000u);  // monotone float->uint
}

__global__ void k_init() {
    int i = blockIdx.x * blockDim.x + threadIdx.x;
    if (i < NN) { g_seg[i] = 0ull; g_owner[i] = -1; }
}

// ---------------------------------------------------------------------------
// Generic fp32 GEMM: C[64 rows x 256 cols per block] = relu?(A[M,K] @ B[K,*] + bias)
// csel: 0 -> Cp, 1 -> g_A, 2 -> g_B
// ---------------------------------------------------------------------------
__global__ __launch_bounds__(256) void k_gemm(
    const float* __restrict__ A, int M, int K, int lda,
    const float* __restrict__ B, int ldb,
    const float* __restrict__ bias,
    float* __restrict__ Cp, int csel, int ldc, int do_relu)
{
    __shared__ float As[32][68];
    __shared__ float Bs[32 * 256];
    float* C = (csel == 1) ? g_A : (csel == 2) ? g_B : Cp;

    const int row0  = blockIdx.x * 64;
    const int gcol0 = blockIdx.y * 256;
    const int tid = threadIdx.x;
    const int cg = tid & 31, eg = tid >> 5;

    float acc[8][8];
    #pragma unroll
    for (int i = 0; i < 8; i++)
        #pragma unroll
        for (int j = 0; j < 8; j++) acc[i][j] = 0.f;

    for (int k0 = 0; k0 < K; k0 += 32) {
        #pragma unroll
        for (int l = 0; l < 8; l++) {
            int idx = tid + l * 256;
            int r = idx >> 5, kk = idx & 31;
            int gr = row0 + r;
            As[kk][r] = (gr < M) ? A[(size_t)gr * lda + k0 + kk] : 0.f;
        }
        #pragma unroll
        for (int l = 0; l < 8; l++) {
            int idx4 = tid + l * 256;           // float4 index
            int kk = idx4 >> 6, c = (idx4 << 2) & 255;
            *(float4*)&Bs[kk * 256 + c] =
                *(const float4*)&B[(size_t)(k0 + kk) * ldb + gcol0 + c];
        }
        __syncthreads();
        #pragma unroll
        for (int kk = 0; kk < 32; kk++) {
            float a[8], b[8];
            *(float4*)(a)     = *(const float4*)&As[kk][eg * 8];
            *(float4*)(a + 4) = *(const float4*)&As[kk][eg * 8 + 4];
            *(float4*)(b)     = *(const float4*)&Bs[kk * 256 + cg * 8];
            *(float4*)(b + 4) = *(const float4*)&Bs[kk * 256 + cg * 8 + 4];
            #pragma unroll
            for (int i = 0; i < 8; i++)
                #pragma unroll
                for (int j = 0; j < 8; j++)
                    acc[i][j] = fmaf(a[i], b[j], acc[i][j]);
        }
        __syncthreads();
    }

    float bb[8];
    #pragma unroll
    for (int j = 0; j < 8; j++) bb[j] = bias ? bias[gcol0 + cg * 8 + j] : 0.f;

    #pragma unroll
    for (int i = 0; i < 8; i++) {
        int gr = row0 + eg * 8 + i;
        if (gr >= M) continue;
        float out[8];
        #pragma unroll
        for (int j = 0; j < 8; j++) {
            float v = acc[i][j] + bb[j];
            out[j] = do_relu ? fmaxf(v, 0.f) : v;
        }
        *(float4*)&C[(size_t)gr * ldc + gcol0 + cg * 8]     = *(float4*)out;
        *(float4*)&C[(size_t)gr * ldc + gcol0 + cg * 8 + 4] = *(float4*)(out + 4);
    }
}

// ---------------------------------------------------------------------------
// MLP2: per entry t: h1 = relu(A[seg] + B[dst]), h = relu(h1@W1 + b1),
//       lk = h . Wlk + blk ; store h, atomic segmax of (lk, t).
// 64 entries/block, K=512 chunked by 32.
// ---------------------------------------------------------------------------
__global__ __launch_bounds__(256) void k_mlp2(
    const float* __restrict__ W1, const float* __restrict__ b1,
    const float* __restrict__ Wlk, const float* __restrict__ blk,
    const int* __restrict__ esrc, const int* __restrict__ edst)
{
    __shared__ float Zs[32][68];
    __shared__ float Bs[32 * 256];
    __shared__ int s_src[64], s_dst[64];

    const int t0 = blockIdx.x * 64;
    const int tid = threadIdx.x;
    const int cg = tid & 31, eg = tid >> 5;

    if (tid < 64) {
        int t = t0 + tid;
        int s = -1, d = -1;
        if (t < TT) {
            if (t < NE) { s = esrc[t]; d = edst[t]; }
            else        { s = t - NE; }
        }
        s_src[tid] = s; s_dst[tid] = d;
    }
    __syncthreads();

    float acc[8][8];
    #pragma unroll
    for (int i = 0; i < 8; i++)
        #pragma unroll
        for (int j = 0; j < 8; j++) acc[i][j] = 0.f;

    for (int k0 = 0; k0 < H0D; k0 += 32) {
        #pragma unroll
        for (int l = 0; l < 8; l++) {
            int idx = tid + l * 256;
            int e = idx >> 5, kk = idx & 31;
            int s = s_src[e];
            float v = 0.f;
            if (s >= 0) {
                v = g_A[(size_t)s * H0D + k0 + kk];
                int d = s_dst[e];
                if (d >= 0) v += g_B[(size_t)d * H0D + k0 + kk];
                v = fmaxf(v, 0.f);
            }
            Zs[kk][e] = v;
        }
        #pragma unroll
        for (int l = 0; l < 8; l++) {
            int idx4 = tid + l * 256;
            int kk = idx4 >> 6, c = (idx4 << 2) & 255;
            *(float4*)&Bs[kk * 256 + c] =
                *(const float4*)&W1[(size_t)(k0 + kk) * H1D + c];
        }
        __syncthreads();
        #pragma unroll
        for (int kk = 0; kk < 32; kk++) {
            float a[8], b[8];
            *(float4*)(a)     = *(const float4*)&Zs[kk][eg * 8];
            *(float4*)(a + 4) = *(const float4*)&Zs[kk][eg * 8 + 4];
            *(float4*)(b)     = *(const float4*)&Bs[kk * 256 + cg * 8];
            *(float4*)(b + 4) = *(const float4*)&Bs[kk * 256 + cg * 8 + 4];
            #pragma unroll
            for (int i = 0; i < 8; i++)
                #pragma unroll
                for (int j = 0; j < 8; j++)
                    acc[i][j] = fmaf(a[i], b[j], acc[i][j]);
        }
        __syncthreads();
    }

    float bb[8], wl[8];
    #pragma unroll
    for (int j = 0; j < 8; j++) {
        bb[j] = b1[cg * 8 + j];
        wl[j] = Wlk[cg * 8 + j];
    }

    float lkp[8];
    #pragma unroll
    for (int i = 0; i < 8; i++) {
        int t = t0 + eg * 8 + i;
        float h[8];
        float p = 0.f;
        #pragma unroll
        for (int j = 0; j < 8; j++) {
            h[j] = fmaxf(acc[i][j] + bb[j], 0.f);
            p = fmaf(h[j], wl[j], p);
        }
        *(float4*)&g_h[(size_t)t * H1D + cg * 8]     = *(float4*)h;
        *(float4*)&g_h[(size_t)t * H1D + cg * 8 + 4] = *(float4*)(h + 4);
        #pragma unroll
        for (int off = 16; off; off >>= 1)
            p += __shfl_xor_sync(0xffffffffu, p, off);
        lkp[i] = p;
    }

    if (cg == 0) {
        float lb = blk[0];
        #pragma unroll
        for (int i = 0; i < 8; i++) {
            int t = t0 + eg * 8 + i;
            if (t < TT) {
                float lk = lkp[i] + lb;
                unsigned long long key =
                    ((unsigned long long)fenc(lk) << 32) | (unsigned int)t;
                atomicMax(&g_seg[s_src[eg * 8 + i]], key);
            }
        }
    }
}

// ---------------------------------------------------------------------------
// Per node: decode winner, action head, register update target (last-i-wins).
// One warp per node.
// ---------------------------------------------------------------------------
__global__ void k_final(const float* __restrict__ Wa, const float* __restrict__ ba,
                        const int* __restrict__ edst)
{
    int warp = (blockIdx.x * blockDim.x + threadIdx.x) >> 5;
    int lane = threadIdx.x & 31;
    if (warp >= NN) return;
    unsigned long long key = g_seg[warp];
    int win = (int)(unsigned int)(key & 0xffffffffull);
    int chosen = (win < NE) ? edst[win] : -1;

    const float* h = &g_h[(size_t)win * H1D];
    float s0 = 0.f, s1 = 0.f;
    #pragma unroll
    for (int j = 0; j < 8; j++) {
        float hv = h[lane + j * 32];
        s0 = fmaf(hv, Wa[(lane + j * 32) * 2 + 0], s0);
        s1 = fmaf(hv, Wa[(lane + j * 32) * 2 + 1], s1);
    }
    #pragma unroll
    for (int off = 16; off; off >>= 1) {
        s0 += __shfl_xor_sync(0xffffffffu, s0, off);
        s1 += __shfl_xor_sync(0xffffffffu, s1, off);
    }
    if (lane == 0) {
        float l0 = s0 + ba[0], l1 = s1 + ba[1];
        if (chosen >= 0 && (l1 > l0))   // at==1 iff strictly greater (argmax tie -> 0)
            atomicMax(&g_owner[chosen], warp);
    }
}

// ---------------------------------------------------------------------------
// Recompute updated rows: out[t] = relu(0.5*(feature[i]+feature[t]) @ We + be)
// One block per target; inactive targets exit.
// ---------------------------------------------------------------------------
__global__ __launch_bounds__(256) void k_newval(
    const float* __restrict__ feature, const float* __restrict__ We,
    const float* __restrict__ be, float* __restrict__ out)
{
    int t = blockIdx.x;
    int i = g_owner[t];
    if (i < 0) return;
    __shared__ float mf[FIN];
    int tid = threadIdx.x;
    for (int k = tid; k < FIN; k += 256)
        mf[k] = 0.5f * (feature[(size_t)i * FIN + k] + feature[(size_t)t * FIN + k]);
    __syncthreads();
    float acc = 0.f;
    #pragma unroll 8
    for (int k = 0; k < FIN; k++)
        acc = fmaf(mf[k], We[(size_t)k * ED + tid], acc);
    out[(size_t)t * ED + tid] = fmaxf(acc + be[tid], 0.f);
}

// ---------------------------------------------------------------------------
extern "C" void kernel_launch(void* const* d_in, const int* in_sizes, int n_in,
                              void* d_out, int out_size) {
    const float* feature = (const float*)d_in[0];
    const float* We      = (const float*)d_in[1];
    const float* be      = (const float*)d_in[2];
    const float* W0      = (const float*)d_in[3];
    const float* b0      = (const float*)d_in[4];
    const float* W1      = (const float*)d_in[5];
    const float* b1      = (const float*)d_in[6];
    const float* Wlk     = (const float*)d_in[7];
    const float* blk     = (const float*)d_in[8];
    const float* Wa      = (const float*)d_in[9];
    const float* ba      = (const float*)d_in[10];
    const int*   esrc    = (const int*)d_in[11];
    const int*   edst    = (const int*)d_in[12];
    float* out = (float*)d_out;

    k_init<<<(NN + 255) / 256, 256>>>();

    // emb = relu(feature @ We + be) -> out (output starts as emb)
    k_gemm<<<dim3((NN + 63) / 64, 1), 256>>>(feature, NN, FIN, FIN,
                                             We, ED, be, out, 0, ED, 1);
    // g_A = emb @ W0[0:256,:] + b0   (bias folded here once)
    k_gemm<<<dim3((NN + 63) / 64, 2), 256>>>(out, NN, ED, ED,
                                             W0, H0D, b0, nullptr, 1, H0D, 0);
    // g_B = emb @ W0[256:512,:]
    k_gemm<<<dim3((NN + 63) / 64, 2), 256>>>(out, NN, ED, ED,
                                             W0 + 256 * H0D, H0D, nullptr,
                                             nullptr, 2, H0D, 0);

    k_mlp2<<<(TT + 63) / 64, 256>>>(W1, b1, Wlk, blk, esrc, edst);
    k_final<<<(NN * 32 + 255) / 256, 256>>>(Wa, ba, edst);
    k_newval<<<NN, 256>>>(feature, We, be, out);
}

// round 6
// speedup vs baseline: 1.7370x; 1.7370x over previous
#include <cuda_runtime.h>
#include <cuda_fp16.h>
#include <cstdint>

#define NN   10000
#define FIN  512
#define ED   256
#define H0D  512
#define H1D  256
#define NE   160000
#define TT   (NE + NN)

#define KCOEF 8e-5f
#define TINY  1.5e-3f

// ------------------------- device scratch (no allocs allowed) ---------------
__device__ float g_A[NN * H0D];                    // emb @ W0[:256,:] + b0
__device__ float g_B[NN * H0D];                    // emb @ W0[256:,:]
__device__ __half g_W1h[H1D * H0D];                // W1^T hi  [256 n][512 k]
__device__ __half g_W1l[H1D * H0D];                // W1^T lo
__device__ float g_C;                              // sum_j ||W1_:j|| * |Wlk_j|
__device__ float g_lk[TT];                         // screened lk
__device__ float g_elk[TT];                        // per-entry error bound
__device__ unsigned int g_segscr[NN];              // per-node max fenc(lk-err)
__device__ unsigned long long g_seg2[NN];          // exact (lk,t) argmax key
__device__ int g_owner[NN];
__device__ int g_ncand;
__device__ int g_cand[TT];
__device__ int g_slot[TT];
__device__ float g_h_cand[(size_t)TT * H1D];       // exact h per candidate slot

__device__ __forceinline__ unsigned int fenc(float f) {
    unsigned int u = __float_as_uint(f);
    return (u & 0x80000000u) ? ~u : (u | 0x80000000u);
}

__device__ __forceinline__ uint32_t smem_u32(const void* p) {
    uint32_t a;
    asm("{ .reg .u64 t; cvta.to.shared.u64 t, %1; cvt.u32.u64 %0, t; }"
        : "=r"(a) : "l"(p));
    return a;
}
__device__ __forceinline__ void ldsm4(uint32_t& r0, uint32_t& r1,
                                      uint32_t& r2, uint32_t& r3, uint32_t a) {
    asm volatile("ldmatrix.sync.aligned.m8n8.x4.shared.b16 {%0,%1,%2,%3}, [%4];"
                 : "=r"(r0), "=r"(r1), "=r"(r2), "=r"(r3) : "r"(a));
}
__device__ __forceinline__ void mma16816(float* c, uint32_t a0, uint32_t a1,
                                         uint32_t a2, uint32_t a3,
                                         uint32_t b0, uint32_t b1) {
    asm volatile("mma.sync.aligned.m16n8k16.row.col.f32.f16.f16.f32 "
        "{%0,%1,%2,%3}, {%4,%5,%6,%7}, {%8,%9}, {%0,%1,%2,%3};"
        : "+f"(c[0]), "+f"(c[1]), "+f"(c[2]), "+f"(c[3])
        : "r"(a0), "r"(a1), "r"(a2), "r"(a3), "r"(b0), "r"(b1));
}

// ------------------------- init ---------------------------------------------
__global__ void k_init() {
    int i = blockIdx.x * blockDim.x + threadIdx.x;
    if (i < NN) { g_segscr[i] = 0u; g_seg2[i] = 0ull; g_owner[i] = -1; }
    if (i == 0) g_ncand = 0;
}

// ------------------------- fp32 GEMM (exact prep path) ----------------------
__global__ __launch_bounds__(256) void k_gemm(
    const float* __restrict__ A, int M, int K, int lda,
    const float* __restrict__ B, int ldb,
    const float* __restrict__ bias,
    float* __restrict__ Cp, int csel, int ldc, int do_relu)
{
    __shared__ float As[32][68];
    __shared__ float Bs[32 * 256];
    float* C = (csel == 1) ? g_A : (csel == 2) ? g_B : Cp;

    const int row0  = blockIdx.x * 64;
    const int gcol0 = blockIdx.y * 256;
    const int tid = threadIdx.x;
    const int cg = tid & 31, eg = tid >> 5;

    float acc[8][8];
    #pragma unroll
    for (int i = 0; i < 8; i++)
        #pragma unroll
        for (int j = 0; j < 8; j++) acc[i][j] = 0.f;

    for (int k0 = 0; k0 < K; k0 += 32) {
        #pragma unroll
        for (int l = 0; l < 8; l++) {
            int idx = tid + l * 256;
            int r = idx >> 5, kk = idx & 31;
            int gr = row0 + r;
            As[kk][r] = (gr < M) ? A[(size_t)gr * lda + k0 + kk] : 0.f;
        }
        #pragma unroll
        for (int l = 0; l < 8; l++) {
            int idx4 = tid + l * 256;
            int kk = idx4 >> 6, c = (idx4 << 2) & 255;
            *(float4*)&Bs[kk * 256 + c] =
                *(const float4*)&B[(size_t)(k0 + kk) * ldb + gcol0 + c];
        }
        __syncthreads();
        #pragma unroll
        for (int kk = 0; kk < 32; kk++) {
            float a[8], b[8];
            *(float4*)(a)     = *(const float4*)&As[kk][eg * 8];
            *(float4*)(a + 4) = *(const float4*)&As[kk][eg * 8 + 4];
            *(float4*)(b)     = *(const float4*)&Bs[kk * 256 + cg * 8];
            *(float4*)(b + 4) = *(const float4*)&Bs[kk * 256 + cg * 8 + 4];
            #pragma unroll
            for (int i = 0; i < 8; i++)
                #pragma unroll
                for (int j = 0; j < 8; j++)
                    acc[i][j] = fmaf(a[i], b[j], acc[i][j]);
        }
        __syncthreads();
    }

    float bb[8];
    #pragma unroll
    for (int j = 0; j < 8; j++) bb[j] = bias ? bias[gcol0 + cg * 8 + j] : 0.f;

    #pragma unroll
    for (int i = 0; i < 8; i++) {
        int gr = row0 + eg * 8 + i;
        if (gr >= M) continue;
        float out[8];
        #pragma unroll
        for (int j = 0; j < 8; j++) {
            float v = acc[i][j] + bb[j];
            out[j] = do_relu ? fmaxf(v, 0.f) : v;
        }
        *(float4*)&C[(size_t)gr * ldc + gcol0 + cg * 8]     = *(float4*)out;
        *(float4*)&C[(size_t)gr * ldc + gcol0 + cg * 8 + 4] = *(float4*)(out + 4);
    }
}

// ------------------------- W1^T fp16 hi/lo split ----------------------------
__global__ void k_prepb(const float* __restrict__ W1) {
    int idx = blockIdx.x * blockDim.x + threadIdx.x;
    if (idx >= H1D * H0D) return;
    int n = idx >> 9, k = idx & 511;
    float w = W1[(size_t)k * H1D + n];
    __half h = __float2half_rn(w);
    g_W1h[idx] = h;
    g_W1l[idx] = __float2half_rn(w - __half2float(h));
}

// ------------------------- C = sum_j ||W1_:j|| * |Wlk_j| --------------------
__global__ void k_prepc(const float* __restrict__ W1,
                        const float* __restrict__ Wlk) {
    __shared__ float red[256];
    int j = threadIdx.x;
    float s = 0.f;
    for (int k = 0; k < H0D; k++) {
        float w = W1[(size_t)k * H1D + j];
        s = fmaf(w, w, s);
    }
    red[j] = sqrtf(s) * fabsf(Wlk[j]);
    __syncthreads();
    for (int o = 128; o; o >>= 1) {
        if (j < o) red[j] += red[j + o];
        __syncthreads();
    }
    if (j == 0) g_C = red[0];
}

// ------------------------- HMMA screening -----------------------------------
// CTA = 64 entries x 256 cols x K=512.  Warp grid 4m x 2n, warp tile 16x128.
// P = Ah*Wh + Al*Wh + Ah*Wl (fp16 mma, fp32 accum).
// Dyn smem (halfs, stride 40): Ah[64][40] Al[64][40] Wh[256][40] Wl[256][40].
#define ASTR 40
#define OFF_AH 0
#define OFF_AL 2560
#define OFF_BH 5120
#define OFF_BL 15360
#define SCREEN_SMEM (25600 * 2)

__global__ void __launch_bounds__(256, 2)
k_screen(const float* __restrict__ b1, const float* __restrict__ Wlk,
         const float* __restrict__ blk,
         const int* __restrict__ esrc, const int* __restrict__ edst)
{
    extern __shared__ __align__(16) __half smh[];
    __half* Ah = smh + OFF_AH;
    __half* Al = smh + OFF_AL;
    __half* Bh = smh + OFF_BH;
    __half* Bl = smh + OFF_BL;

    __shared__ float s_n2[64];
    __shared__ float s_lk[2][64];
    __shared__ int s_src[64], s_dst[64];
    __shared__ float s_b1[256], s_wlk[256];

    const int tid = threadIdx.x, wid = tid >> 5, lane = tid & 31;
    const int wm = wid & 3, wn = wid >> 2;
    const int m0 = wm * 16;
    const int t0 = blockIdx.x * 64;

    if (tid < 64) {
        int t = t0 + tid;
        int s = -1, d = -1;
        if (t < TT) {
            if (t < NE) { s = esrc[t]; d = edst[t]; }
            else        { s = t - NE; }
        }
        s_src[tid] = s; s_dst[tid] = d;
        s_n2[tid] = 0.f;
    }
    s_b1[tid]  = b1[tid];
    s_wlk[tid] = Wlk[tid];
    __syncthreads();

    // staging assignment: 4 threads per row, 8 k each
    const int ar = tid >> 2, kq = (tid & 3) * 8;
    const int ss = s_src[ar], dd = s_dst[ar];
    const float4* pA = (const float4*)(g_A + (size_t)(ss < 0 ? 0 : ss) * H0D);
    const float4* pB = (const float4*)(g_B + (size_t)(dd < 0 ? 0 : dd) * H0D);

    // ldmatrix base addresses
    const uint32_t sb = smem_u32(smh);
    const uint32_t aRow = m0 + (lane & 15);
    const uint32_t aCol = (lane < 16) ? 0 : 8;
    const uint32_t bRow0 = wn * 128 + (lane & 7) + ((lane >= 16) ? 8 : 0);
    const uint32_t bCol = (lane & 8) ? 8 : 0;

    float acc[16][4];
    #pragma unroll
    for (int i = 0; i < 16; i++)
        #pragma unroll
        for (int j = 0; j < 4; j++) acc[i][j] = 0.f;

    for (int kb = 0; kb < 16; kb++) {
        // ---- stage A (hi/lo fp16 of relu(gA[s]+gB[d])) + norm2 -------------
        {
            int f4 = kb * 8 + (tid & 3) * 2;
            float4 a0 = make_float4(0.f, 0.f, 0.f, 0.f), a1 = a0;
            if (ss >= 0) {
                a0 = pA[f4]; a1 = pA[f4 + 1];
                if (dd >= 0) {
                    float4 q0 = pB[f4], q1 = pB[f4 + 1];
                    a0.x += q0.x; a0.y += q0.y; a0.z += q0.z; a0.w += q0.w;
                    a1.x += q1.x; a1.y += q1.y; a1.z += q1.z; a1.w += q1.w;
                }
            }
            float v[8] = {a0.x, a0.y, a0.z, a0.w, a1.x, a1.y, a1.z, a1.w};
            float n2 = 0.f;
            __half* dh = Ah + ar * ASTR + kq;
            __half* dl = Al + ar * ASTR + kq;
            #pragma unroll
            for (int e = 0; e < 8; e++) {
                float x = fmaxf(v[e], 0.f);
                __half hh = __float2half_rn(x);
                dh[e] = hh;
                dl[e] = __float2half_rn(x - __half2float(hh));
                n2 = fmaf(x, x, n2);
            }
            if (ss >= 0) atomicAdd(&s_n2[ar], n2);
        }
        // ---- stage B (W1^T hi/lo chunk): n = tid --------------------------
        {
            const uint4* qh = (const uint4*)(g_W1h + (size_t)tid * H0D + kb * 32);
            const uint4* ql = (const uint4*)(g_W1l + (size_t)tid * H0D + kb * 32);
            uint4* th = (uint4*)(Bh + (size_t)tid * ASTR);
            uint4* tl = (uint4*)(Bl + (size_t)tid * ASTR);
            #pragma unroll
            for (int q = 0; q < 4; q++) { th[q] = qh[q]; tl[q] = ql[q]; }
        }
        __syncthreads();

        // ---- compute: 2 k16 steps ------------------------------------------
        #pragma unroll
        for (int ks = 0; ks < 2; ks++) {
            const uint32_t kofs = ks * 16;
            uint32_t ah0, ah1, ah2, ah3, al0, al1, al2, al3;
            ldsm4(ah0, ah1, ah2, ah3,
                  sb + (OFF_AH + aRow * ASTR + aCol + kofs) * 2);
            ldsm4(al0, al1, al2, al3,
                  sb + (OFF_AL + aRow * ASTR + aCol + kofs) * 2);
            #pragma unroll
            for (int ntp = 0; ntp < 8; ntp++) {
                uint32_t brow = bRow0 + ntp * 16;
                uint32_t bh0, bh1, bh2, bh3, bl0, bl1, bl2, bl3;
                ldsm4(bh0, bh1, bh2, bh3,
                      sb + (OFF_BH + brow * ASTR + bCol + kofs) * 2);
                ldsm4(bl0, bl1, bl2, bl3,
                      sb + (OFF_BL + brow * ASTR + bCol + kofs) * 2);
                float* c0 = acc[ntp * 2];
                float* c1 = acc[ntp * 2 + 1];
                mma16816(c0, ah0, ah1, ah2, ah3, bh0, bh1);
                mma16816(c0, al0, al1, al2, al3, bh0, bh1);
                mma16816(c0, ah0, ah1, ah2, ah3, bl0, bl1);
                mma16816(c1, ah0, ah1, ah2, ah3, bh2, bh3);
                mma16816(c1, al0, al1, al2, al3, bh2, bh3);
                mma16816(c1, ah0, ah1, ah2, ah3, bl2, bl3);
            }
        }
        __syncthreads();
    }

    // ---- epilogue: lk = sum_j relu(P + b1_j) * wlk_j ------------------------
    const int g = lane >> 2, tg = lane & 3;
    float sum0 = 0.f, sum1 = 0.f;
    #pragma unroll
    for (int nt = 0; nt < 16; nt++) {
        int c0 = wn * 128 + nt * 8 + tg * 2;
        float b10 = s_b1[c0],     w0 = s_wlk[c0];
        float b11 = s_b1[c0 + 1], w1 = s_wlk[c0 + 1];
        sum0 += fmaxf(acc[nt][0] + b10, 0.f) * w0 +
                fmaxf(acc[nt][1] + b11, 0.f) * w1;
        sum1 += fmaxf(acc[nt][2] + b10, 0.f) * w0 +
                fmaxf(acc[nt][3] + b11, 0.f) * w1;
    }
    sum0 += __shfl_xor_sync(0xffffffffu, sum0, 1);
    sum0 += __shfl_xor_sync(0xffffffffu, sum0, 2);
    sum1 += __shfl_xor_sync(0xffffffffu, sum1, 1);
    sum1 += __shfl_xor_sync(0xffffffffu, sum1, 2);
    if (tg == 0) {
        s_lk[wn][m0 + g]     = sum0;
        s_lk[wn][m0 + g + 8] = sum1;
    }
    __syncthreads();

    if (tid < 64) {
        int t = t0 + tid;
        if (t < TT) {
            float lk = s_lk[0][tid] + s_lk[1][tid] + blk[0];
            float err = KCOEF * g_C * sqrtf(s_n2[tid]) + TINY;
            g_lk[t] = lk;
            g_elk[t] = err;
            atomicMax(&g_segscr[s_src[tid]], fenc(lk - err));
        }
    }
}

// ------------------------- candidate compaction -----------------------------
__global__ void k_compact(const int* __restrict__ esrc) {
    int t = blockIdx.x * blockDim.x + threadIdx.x;
    if (t >= TT) return;
    int s = (t < NE) ? esrc[t] : (t - NE);
    if (fenc(g_lk[t] + g_elk[t]) >= g_segscr[s]) {
        int slot = atomicAdd(&g_ncand, 1);
        g_cand[slot] = t;
        g_slot[t] = slot;
    }
}

// ------------------------- exact fp32 rescore of candidates -----------------
__global__ __launch_bounds__(256) void k_rescore(
    const float* __restrict__ W1, const float* __restrict__ b1,
    const float* __restrict__ Wlk, const float* __restrict__ blk,
    const int* __restrict__ esrc, const int* __restrict__ edst)
{
    const int c0 = blockIdx.x * 64;
    const int nc = g_ncand;
    if (c0 >= nc) return;

    __shared__ float Zs[32][68];
    __shared__ float Bs[32 * 256];
    __shared__ int s_src[64], s_dst[64], s_t[64];

    const int tid = threadIdx.x;
    const int cg = tid & 31, eg = tid >> 5;

    if (tid < 64) {
        int c = c0 + tid;
        int s = -1, d = -1, t = -1;
        if (c < nc) {
            t = g_cand[c];
            if (t < NE) { s = esrc[t]; d = edst[t]; }
            else        { s = t - NE; }
        }
        s_src[tid] = s; s_dst[tid] = d; s_t[tid] = t;
    }
    __syncthreads();

    float acc[8][8];
    #pragma unroll
    for (int i = 0; i < 8; i++)
        #pragma unroll
        for (int j = 0; j < 8; j++) acc[i][j] = 0.f;

    for (int k0 = 0; k0 < H0D; k0 += 32) {
        #pragma unroll
        for (int l = 0; l < 8; l++) {
            int idx = tid + l * 256;
            int e = idx >> 5, kk = idx & 31;
            int s = s_src[e];
            float v = 0.f;
            if (s >= 0) {
                v = g_A[(size_t)s * H0D + k0 + kk];
                int d = s_dst[e];
                if (d >= 0) v += g_B[(size_t)d * H0D + k0 + kk];
                v = fmaxf(v, 0.f);
            }
            Zs[kk][e] = v;
        }
        #pragma unroll
        for (int l = 0; l < 8; l++) {
            int idx4 = tid + l * 256;
            int kk = idx4 >> 6, c = (idx4 << 2) & 255;
            *(float4*)&Bs[kk * 256 + c] =
                *(const float4*)&W1[(size_t)(k0 + kk) * H1D + c];
        }
        __syncthreads();
        #pragma unroll
        for (int kk = 0; kk < 32; kk++) {
            float a[8], b[8];
            *(float4*)(a)     = *(const float4*)&Zs[kk][eg * 8];
            *(float4*)(a + 4) = *(const float4*)&Zs[kk][eg * 8 + 4];
            *(float4*)(b)     = *(const float4*)&Bs[kk * 256 + cg * 8];
            *(float4*)(b + 4) = *(const float4*)&Bs[kk * 256 + cg * 8 + 4];
            #pragma unroll
            for (int i = 0; i < 8; i++)
                #pragma unroll
                for (int j = 0; j < 8; j++)
                    acc[i][j] = fmaf(a[i], b[j], acc[i][j]);
        }
        __syncthreads();
    }

    float bb[8], wl[8];
    #pragma unroll
    for (int j = 0; j < 8; j++) {
        bb[j] = b1[cg * 8 + j];
        wl[j] = Wlk[cg * 8 + j];
    }

    float lkp[8];
    #pragma unroll
    for (int i = 0; i < 8; i++) {
        int e = eg * 8 + i;
        int c = c0 + e;
        float h[8];
        float p = 0.f;
        #pragma unroll
        for (int j = 0; j < 8; j++) {
            h[j] = fmaxf(acc[i][j] + bb[j], 0.f);
            p = fmaf(h[j], wl[j], p);
        }
        if (s_t[e] >= 0) {
            *(float4*)&g_h_cand[(size_t)c * H1D + cg * 8]     = *(float4*)h;
            *(float4*)&g_h_cand[(size_t)c * H1D + cg * 8 + 4] = *(float4*)(h + 4);
        }
        #pragma unroll
        for (int off = 16; off; off >>= 1)
            p += __shfl_xor_sync(0xffffffffu, p, off);
        lkp[i] = p;
    }

    if (cg == 0) {
        float lb = blk[0];
        #pragma unroll
        for (int i = 0; i < 8; i++) {
            int e = eg * 8 + i;
            int t = s_t[e];
            if (t >= 0) {
                float lk = lkp[i] + lb;
                unsigned long long key =
                    ((unsigned long long)fenc(lk) << 32) | (unsigned int)t;
                atomicMax(&g_seg2[s_src[e]], key);
            }
        }
    }
}

// ------------------------- winner decode + action head ----------------------
__global__ void k_final(const float* __restrict__ Wa, const float* __restrict__ ba,
                        const int* __restrict__ edst)
{
    int warp = (blockIdx.x * blockDim.x + threadIdx.x) >> 5;
    int lane = threadIdx.x & 31;
    if (warp >= NN) return;
    unsigned long long key = g_seg2[warp];
    int win = (int)(unsigned int)(key & 0xffffffffull);
    int chosen = (win < NE) ? edst[win] : -1;

    const float* h = &g_h_cand[(size_t)g_slot[win] * H1D];
    float s0 = 0.f, s1 = 0.f;
    #pragma unroll
    for (int j = 0; j < 8; j++) {
        float hv = h[lane + j * 32];
        s0 = fmaf(hv, Wa[(lane + j * 32) * 2 + 0], s0);
        s1 = fmaf(hv, Wa[(lane + j * 32) * 2 + 1], s1);
    }
    #pragma unroll
    for (int off = 16; off; off >>= 1) {
        s0 += __shfl_xor_sync(0xffffffffu, s0, off);
        s1 += __shfl_xor_sync(0xffffffffu, s1, off);
    }
    if (lane == 0) {
        float l0 = s0 + ba[0], l1 = s1 + ba[1];
        if (chosen >= 0 && (l1 > l0))
            atomicMax(&g_owner[chosen], warp);
    }
}

// ------------------------- recompute updated rows ---------------------------
__global__ __launch_bounds__(256) void k_newval(
    const float* __restrict__ feature, const float* __restrict__ We,
    const float* __restrict__ be, float* __restrict__ out)
{
    int t = blockIdx.x;
    int i = g_owner[t];
    if (i < 0) return;
    __shared__ float mf[FIN];
    int tid = threadIdx.x;
    for (int k = tid; k < FIN; k += 256)
        mf[k] = 0.5f * (feature[(size_t)i * FIN + k] + feature[(size_t)t * FIN + k]);
    __syncthreads();
    float acc = 0.f;
    #pragma unroll 8
    for (int k = 0; k < FIN; k++)
        acc = fmaf(mf[k], We[(size_t)k * ED + tid], acc);
    out[(size_t)t * ED + tid] = fmaxf(acc + be[tid], 0.f);
}

// ---------------------------------------------------------------------------
extern "C" void kernel_launch(void* const* d_in, const int* in_sizes, int n_in,
                              void* d_out, int out_size) {
    const float* feature = (const float*)d_in[0];
    const float* We      = (const float*)d_in[1];
    const float* be      = (const float*)d_in[2];
    const float* W0      = (const float*)d_in[3];
    const float* b0      = (const float*)d_in[4];
    const float* W1      = (const float*)d_in[5];
    const float* b1      = (const float*)d_in[6];
    const float* Wlk     = (const float*)d_in[7];
    const float* blk     = (const float*)d_in[8];
    const float* Wa      = (const float*)d_in[9];
    const float* ba      = (const float*)d_in[10];
    const int*   esrc    = (const int*)d_in[11];
    const int*   edst    = (const int*)d_in[12];
    float* out = (float*)d_out;

    static int smem_set = 0;
    if (!smem_set) {
        cudaFuncSetAttribute(k_screen,
                             cudaFuncAttributeMaxDynamicSharedMemorySize,
                             SCREEN_SMEM);
        smem_set = 1;
    }

    k_init<<<(NN + 255) / 256, 256>>>();
    k_prepb<<<(H1D * H0D + 255) / 256, 256>>>(W1);
    k_prepc<<<1, 256>>>(W1, Wlk);

    // emb = relu(feature @ We + be) -> out
    k_gemm<<<dim3((NN + 63) / 64, 1), 256>>>(feature, NN, FIN, FIN,
                                             We, ED, be, out, 0, ED, 1);
    // g_A = emb @ W0[0:256,:] + b0
    k_gemm<<<dim3((NN + 63) / 64, 2), 256>>>(out, NN, ED, ED,
                                             W0, H0D, b0, nullptr, 1, H0D, 0);
    // g_B = emb @ W0[256:512,:]
    k_gemm<<<dim3((NN + 63) / 64, 2), 256>>>(out, NN, ED, ED,
                                             W0 + 256 * H0D, H0D, nullptr,
                                             nullptr, 2, H0D, 0);

    k_screen<<<(TT + 63) / 64, 256, SCREEN_SMEM>>>(b1, Wlk, blk, esrc, edst);
    k_compact<<<(TT + 255) / 256, 256>>>(esrc);
    k_rescore<<<(TT + 63) / 64, 256>>>(W1, b1, Wlk, blk, esrc, edst);
    k_final<<<(NN * 32 + 255) / 256, 256>>>(Wa, ba, edst);
    k_newval<<<NN, 256>>>(feature, We, be, out);
}

// round 8
// speedup vs baseline: 1.9209x; 1.1058x over previous
#include <cuda_runtime.h>
#include <cuda_fp16.h>
#include <cstdint>

#define NN   10000
#define FIN  512
#define ED   256
#define H0D  512
#define H1D  256
#define NE   160000
#define TT   (NE + NN)

#define KCOEF 8e-5f
#define TINY  1.5e-3f

// ------------------------- device scratch (no allocs allowed) ---------------
__device__ float g_A[NN * H0D];                    // emb @ W0[:256,:] + b0
__device__ float g_B[NN * H0D];                    // emb @ W0[256:,:]
__device__ __half g_W1h[H1D * H0D];                // W1^T hi  [256 n][512 k]
__device__ __half g_W1l[H1D * H0D];                // W1^T lo
__device__ __half g_Weh[ED * FIN];                 // We^T hi  [256 n][512 k]
__device__ __half g_Wel[ED * FIN];                 // We^T lo
__device__ __half g_W0h[H0D * H0D];                // W0^T hi  [512 n][512 k]
__device__ __half g_W0l[H0D * H0D];                // W0^T lo
__device__ float g_C;                              // sum_j ||W1_:j|| * |Wlk_j|
__device__ float g_lk[TT];                         // screened lk
__device__ float g_elk[TT];                        // per-entry error bound
__device__ unsigned int g_segscr[NN];              // per-node max fenc(lk-err)
__device__ unsigned long long g_seg2[NN];          // exact (lk,t) argmax key
__device__ int g_owner[NN];
__device__ int g_ncand;
__device__ int g_cand[TT];
__device__ int g_slot[TT];
__device__ float g_h_cand[(size_t)TT * H1D];       // exact h per candidate slot

__device__ __forceinline__ unsigned int fenc(float f) {
    unsigned int u = __float_as_uint(f);
    return (u & 0x80000000u) ? ~u : (u | 0x80000000u);
}

__device__ __forceinline__ uint32_t smem_u32(const void* p) {
    uint32_t a;
    asm("{ .reg .u64 t; cvta.to.shared.u64 t, %1; cvt.u32.u64 %0, t; }"
        : "=r"(a) : "l"(p));
    return a;
}
__device__ __forceinline__ void ldsm4(uint32_t& r0, uint32_t& r1,
                                      uint32_t& r2, uint32_t& r3, uint32_t a) {
    asm volatile("ldmatrix.sync.aligned.m8n8.x4.shared.b16 {%0,%1,%2,%3}, [%4];"
                 : "=r"(r0), "=r"(r1), "=r"(r2), "=r"(r3) : "r"(a));
}
__device__ __forceinline__ void mma16816(float* c, uint32_t a0, uint32_t a1,
                                         uint32_t a2, uint32_t a3,
                                         uint32_t b0, uint32_t b1) {
    asm volatile("mma.sync.aligned.m16n8k16.row.col.f32.f16.f16.f32 "
        "{%0,%1,%2,%3}, {%4,%5,%6,%7}, {%8,%9}, {%0,%1,%2,%3};"
        : "+f"(c[0]), "+f"(c[1]), "+f"(c[2]), "+f"(c[3])
        : "r"(a0), "r"(a1), "r"(a2), "r"(a3), "r"(b0), "r"(b1));
}

// ------------------------- init ---------------------------------------------
__global__ void k_init() {
    int i = blockIdx.x * blockDim.x + threadIdx.x;
    if (i < NN) { g_segscr[i] = 0u; g_seg2[i] = 0ull; g_owner[i] = -1; }
    if (i == 0) g_ncand = 0;
}

// ------------------------- weight transpose + fp16 hi/lo splits -------------
__global__ void k_prepw(const float* __restrict__ W1,
                        const float* __restrict__ We,
                        const float* __restrict__ W0) {
    int idx = blockIdx.x * blockDim.x + threadIdx.x;
    // W1^T [256][512]
    if (idx < H1D * H0D) {
        int n = idx >> 9, k = idx & 511;
        float w = W1[(size_t)k * H1D + n];
        __half h = __float2half_rn(w);
        g_W1h[idx] = h;
        g_W1l[idx] = __float2half_rn(w - __half2float(h));
    }
    // We^T [256][512]
    if (idx < ED * FIN) {
        int n = idx >> 9, k = idx & 511;
        float w = We[(size_t)k * ED + n];
        __half h = __float2half_rn(w);
        g_Weh[idx] = h;
        g_Wel[idx] = __float2half_rn(w - __half2float(h));
    }
    // W0^T [512][512]
    if (idx < H0D * H0D) {
        int n = idx >> 9, k = idx & 511;
        float w = W0[(size_t)k * H0D + n];
        __half h = __float2half_rn(w);
        g_W0h[idx] = h;
        g_W0l[idx] = __float2half_rn(w - __half2float(h));
    }
}

// ------------------------- C = sum_j ||W1_:j|| * |Wlk_j| --------------------
__global__ void k_prepc(const float* __restrict__ W1,
                        const float* __restrict__ Wlk) {
    __shared__ float red[256];
    int j = threadIdx.x;
    float s = 0.f;
    for (int k = 0; k < H0D; k++) {
        float w = W1[(size_t)k * H1D + j];
        s = fmaf(w, w, s);
    }
    red[j] = sqrtf(s) * fabsf(Wlk[j]);
    __syncthreads();
    for (int o = 128; o; o >>= 1) {
        if (j < o) red[j] += red[j + o];
        __syncthreads();
    }
    if (j == 0) g_C = red[0];
}

// ------------------------- shared HMMA tile constants -----------------------
#define ASTR 40
#define OFF_AH 0
#define OFF_AL 2560
#define OFF_BH 5120
#define OFF_BL 15360
#define HMMA_SMEM (25600 * 2)

// ------------------------- split-HMMA GEMM (prep path) ----------------------
// C[64 x 256 per CTA] = relu?(A[M,K] @ BT^T + bias), 3-term fp16 split.
// BT is pre-transposed/split fp16 [Ntot n][512 k] (row stride 512).
// bsel: 0 -> We^T, 1 -> W0^T.  csel: 0 -> Cp, 1 -> g_A, 2 -> g_B (z-fused).
__global__ void __launch_bounds__(256, 2)
k_hgemm(const float* __restrict__ A, int lda, int M, int nkb,
        int bsel, int zfuse, const float* __restrict__ bias,
        float* __restrict__ Cp, int csel0, int ldc, int do_relu)
{
    extern __shared__ __align__(16) __half smh[];
    __half* Ah = smh + OFF_AH;
    __half* Al = smh + OFF_AL;
    __half* Bh = smh + OFF_BH;
    __half* Bl = smh + OFF_BL;
    __shared__ float s_bias[256];

    const int z = zfuse ? blockIdx.z : 0;
    const int csel = csel0 + z;
    const int koff = z * 256;
    float* C = (csel == 1) ? g_A : (csel == 2) ? g_B : Cp;
    const __half* BTh = bsel ? g_W0h : g_Weh;
    const __half* BTl = bsel ? g_W0l : g_Wel;
    const float* bias_eff = (csel == 2) ? nullptr : bias;

    const int tid = threadIdx.x, wid = tid >> 5, lane = tid & 31;
    const int wm = wid & 3, wn = wid >> 2;
    const int m0 = wm * 16;
    const int row0 = blockIdx.x * 64;
    const int n0 = blockIdx.y * 256;

    s_bias[tid] = bias_eff ? bias_eff[n0 + tid] : 0.f;

    const int ar = tid >> 2, kq = (tid & 3) * 8;
    const int grow = row0 + ar;
    const float4* pA = (const float4*)(A + (size_t)(grow < M ? grow : 0) * lda);

    const uint32_t sb = smem_u32(smh);
    const uint32_t aRow = m0 + (lane & 15);
    const uint32_t aCol = (lane < 16) ? 0 : 8;
    const uint32_t bRow0 = wn * 128 + (lane & 7) + ((lane >= 16) ? 8 : 0);
    const uint32_t bCol = (lane & 8) ? 8 : 0;

    float acc[16][4];
    #pragma unroll
    for (int i = 0; i < 16; i++)
        #pragma unroll
        for (int j = 0; j < 4; j++) acc[i][j] = 0.f;

    for (int kb = 0; kb < nkb; kb++) {
        // ---- stage A: hi/lo fp16 of A row chunk ----------------------------
        {
            int f4 = kb * 8 + (tid & 3) * 2;
            float4 a0 = make_float4(0.f, 0.f, 0.f, 0.f), a1 = a0;
            if (grow < M) { a0 = pA[f4]; a1 = pA[f4 + 1]; }
            float v[8] = {a0.x, a0.y, a0.z, a0.w, a1.x, a1.y, a1.z, a1.w};
            __half* dh = Ah + ar * ASTR + kq;
            __half* dl = Al + ar * ASTR + kq;
            #pragma unroll
            for (int e = 0; e < 8; e++) {
                __half hh = __float2half_rn(v[e]);
                dh[e] = hh;
                dl[e] = __float2half_rn(v[e] - __half2float(hh));
            }
        }
        // ---- stage B: pre-split BT row chunk (n = n0+tid) ------------------
        {
            const uint4* qh = (const uint4*)(BTh + (size_t)(n0 + tid) * 512 +
                                             koff + kb * 32);
            const uint4* ql = (const uint4*)(BTl + (size_t)(n0 + tid) * 512 +
                                             koff + kb * 32);
            uint4* th = (uint4*)(Bh + (size_t)tid * ASTR);
            uint4* tl = (uint4*)(Bl + (size_t)tid * ASTR);
            #pragma unroll
            for (int q = 0; q < 4; q++) { th[q] = qh[q]; tl[q] = ql[q]; }
        }
        __syncthreads();

        #pragma unroll
        for (int ks = 0; ks < 2; ks++) {
            const uint32_t kofs = ks * 16;
            uint32_t ah0, ah1, ah2, ah3, al0, al1, al2, al3;
            ldsm4(ah0, ah1, ah2, ah3,
                  sb + (OFF_AH + aRow * ASTR + aCol + kofs) * 2);
            ldsm4(al0, al1, al2, al3,
                  sb + (OFF_AL + aRow * ASTR + aCol + kofs) * 2);
            #pragma unroll
            for (int ntp = 0; ntp < 8; ntp++) {
                uint32_t brow = bRow0 + ntp * 16;
                uint32_t bh0, bh1, bh2, bh3, bl0, bl1, bl2, bl3;
                ldsm4(bh0, bh1, bh2, bh3,
                      sb + (OFF_BH + brow * ASTR + bCol + kofs) * 2);
                ldsm4(bl0, bl1, bl2, bl3,
                      sb + (OFF_BL + brow * ASTR + bCol + kofs) * 2);
                float* c0 = acc[ntp * 2];
                float* c1 = acc[ntp * 2 + 1];
                mma16816(c0, ah0, ah1, ah2, ah3, bh0, bh1);
                mma16816(c0, al0, al1, al2, al3, bh0, bh1);
                mma16816(c0, ah0, ah1, ah2, ah3, bl0, bl1);
                mma16816(c1, ah0, ah1, ah2, ah3, bh2, bh3);
                mma16816(c1, al0, al1, al2, al3, bh2, bh3);
                mma16816(c1, ah0, ah1, ah2, ah3, bl2, bl3);
            }
        }
        __syncthreads();
    }

    // ---- epilogue: bias (+relu), write fp32 C ------------------------------
    const int g = lane >> 2, tg = lane & 3;
    const int r0 = row0 + m0 + g;
    const int r1 = r0 + 8;
    #pragma unroll
    for (int nt = 0; nt < 16; nt++) {
        int c = wn * 128 + nt * 8 + tg * 2;
        float b0v = s_bias[c], b1v = s_bias[c + 1];
        float v00 = acc[nt][0] + b0v, v01 = acc[nt][1] + b1v;
        float v10 = acc[nt][2] + b0v, v11 = acc[nt][3] + b1v;
        if (do_relu) {
            v00 = fmaxf(v00, 0.f); v01 = fmaxf(v01, 0.f);
            v10 = fmaxf(v10, 0.f); v11 = fmaxf(v11, 0.f);
        }
        if (r0 < M) *(float2*)&C[(size_t)r0 * ldc + n0 + c] = make_float2(v00, v01);
        if (r1 < M) *(float2*)&C[(size_t)r1 * ldc + n0 + c] = make_float2(v10, v11);
    }
}

// ------------------------- HMMA screening -----------------------------------
__global__ void __launch_bounds__(256, 2)
k_screen(const float* __restrict__ b1, const float* __restrict__ Wlk,
         const float* __restrict__ blk,
         const int* __restrict__ esrc, const int* __restrict__ edst)
{
    extern __shared__ __align__(16) __half smh[];
    __half* Ah = smh + OFF_AH;
    __half* Al = smh + OFF_AL;
    __half* Bh = smh + OFF_BH;
    __half* Bl = smh + OFF_BL;

    __shared__ float s_n2[64];
    __shared__ float s_lk[2][64];
    __shared__ int s_src[64], s_dst[64];
    __shared__ float s_b1[256], s_wlk[256];

    const int tid = threadIdx.x, wid = tid >> 5, lane = tid & 31;
    const int wm = wid & 3, wn = wid >> 2;
    const int m0 = wm * 16;
    const int t0 = blockIdx.x * 64;

    if (tid < 64) {
        int t = t0 + tid;
        int s = -1, d = -1;
        if (t < TT) {
            if (t < NE) { s = esrc[t]; d = edst[t]; }
            else        { s = t - NE; }
        }
        s_src[tid] = s; s_dst[tid] = d;
        s_n2[tid] = 0.f;
    }
    s_b1[tid]  = b1[tid];
    s_wlk[tid] = Wlk[tid];
    __syncthreads();

    const int ar = tid >> 2, kq = (tid & 3) * 8;
    const int ss = s_src[ar], dd = s_dst[ar];
    const float4* pA = (const float4*)(g_A + (size_t)(ss < 0 ? 0 : ss) * H0D);
    const float4* pB = (const float4*)(g_B + (size_t)(dd < 0 ? 0 : dd) * H0D);

    const uint32_t sb = smem_u32(smh);
    const uint32_t aRow = m0 + (lane & 15);
    const uint32_t aCol = (lane < 16) ? 0 : 8;
    const uint32_t bRow0 = wn * 128 + (lane & 7) + ((lane >= 16) ? 8 : 0);
    const uint32_t bCol = (lane & 8) ? 8 : 0;

    float acc[16][4];
    #pragma unroll
    for (int i = 0; i < 16; i++)
        #pragma unroll
        for (int j = 0; j < 4; j++) acc[i][j] = 0.f;

    for (int kb = 0; kb < 16; kb++) {
        {
            int f4 = kb * 8 + (tid & 3) * 2;
            float4 a0 = make_float4(0.f, 0.f, 0.f, 0.f), a1 = a0;
            if (ss >= 0) {
                a0 = pA[f4]; a1 = pA[f4 + 1];
                if (dd >= 0) {
                    float4 q0 = pB[f4], q1 = pB[f4 + 1];
                    a0.x += q0.x; a0.y += q0.y; a0.z += q0.z; a0.w += q0.w;
                    a1.x += q1.x; a1.y += q1.y; a1.z += q1.z; a1.w += q1.w;
                }
            }
            float v[8] = {a0.x, a0.y, a0.z, a0.w, a1.x, a1.y, a1.z, a1.w};
            float n2 = 0.f;
            __half* dh = Ah + ar * ASTR + kq;
            __half* dl = Al + ar * ASTR + kq;
            #pragma unroll
            for (int e = 0; e < 8; e++) {
                float x = fmaxf(v[e], 0.f);
                __half hh = __float2half_rn(x);
                dh[e] = hh;
                dl[e] = __float2half_rn(x - __half2float(hh));
                n2 = fmaf(x, x, n2);
            }
            if (ss >= 0) atomicAdd(&s_n2[ar], n2);
        }
        {
            const uint4* qh = (const uint4*)(g_W1h + (size_t)tid * H0D + kb * 32);
            const uint4* ql = (const uint4*)(g_W1l + (size_t)tid * H0D + kb * 32);
            uint4* th = (uint4*)(Bh + (size_t)tid * ASTR);
            uint4* tl = (uint4*)(Bl + (size_t)tid * ASTR);
            #pragma unroll
            for (int q = 0; q < 4; q++) { th[q] = qh[q]; tl[q] = ql[q]; }
        }
        __syncthreads();

        #pragma unroll
        for (int ks = 0; ks < 2; ks++) {
            const uint32_t kofs = ks * 16;
            uint32_t ah0, ah1, ah2, ah3, al0, al1, al2, al3;
            ldsm4(ah0, ah1, ah2, ah3,
                  sb + (OFF_AH + aRow * ASTR + aCol + kofs) * 2);
            ldsm4(al0, al1, al2, al3,
                  sb + (OFF_AL + aRow * ASTR + aCol + kofs) * 2);
            #pragma unroll
            for (int ntp = 0; ntp < 8; ntp++) {
                uint32_t brow = bRow0 + ntp * 16;
                uint32_t bh0, bh1, bh2, bh3, bl0, bl1, bl2, bl3;
                ldsm4(bh0, bh1, bh2, bh3,
                      sb + (OFF_BH + brow * ASTR + bCol + kofs) * 2);
                ldsm4(bl0, bl1, bl2, bl3,
                      sb + (OFF_BL + brow * ASTR + bCol + kofs) * 2);
                float* c0 = acc[ntp * 2];
                float* c1 = acc[ntp * 2 + 1];
                mma16816(c0, ah0, ah1, ah2, ah3, bh0, bh1);
                mma16816(c0, al0, al1, al2, al3, bh0, bh1);
                mma16816(c0, ah0, ah1, ah2, ah3, bl0, bl1);
                mma16816(c1, ah0, ah1, ah2, ah3, bh2, bh3);
                mma16816(c1, al0, al1, al2, al3, bh2, bh3);
                mma16816(c1, ah0, ah1, ah2, ah3, bl2, bl3);
            }
        }
        __syncthreads();
    }

    const int g = lane >> 2, tg = lane & 3;
    float sum0 = 0.f, sum1 = 0.f;
    #pragma unroll
    for (int nt = 0; nt < 16; nt++) {
        int c0 = wn * 128 + nt * 8 + tg * 2;
        float b10 = s_b1[c0],     w0 = s_wlk[c0];
        float b11 = s_b1[c0 + 1], w1 = s_wlk[c0 + 1];
        sum0 += fmaxf(acc[nt][0] + b10, 0.f) * w0 +
                fmaxf(acc[nt][1] + b11, 0.f) * w1;
        sum1 += fmaxf(acc[nt][2] + b10, 0.f) * w0 +
                fmaxf(acc[nt][3] + b11, 0.f) * w1;
    }
    sum0 += __shfl_xor_sync(0xffffffffu, sum0, 1);
    sum0 += __shfl_xor_sync(0xffffffffu, sum0, 2);
    sum1 += __shfl_xor_sync(0xffffffffu, sum1, 1);
    sum1 += __shfl_xor_sync(0xffffffffu, sum1, 2);
    if (tg == 0) {
        s_lk[wn][m0 + g]     = sum0;
        s_lk[wn][m0 + g + 8] = sum1;
    }
    __syncthreads();

    if (tid < 64) {
        int t = t0 + tid;
        if (t < TT) {
            float lk = s_lk[0][tid] + s_lk[1][tid] + blk[0];
            float err = KCOEF * g_C * sqrtf(s_n2[tid]) + TINY;
            g_lk[t] = lk;
            g_elk[t] = err;
            atomicMax(&g_segscr[s_src[tid]], fenc(lk - err));
        }
    }
}

// ------------------------- candidate compaction -----------------------------
__global__ void k_compact(const int* __restrict__ esrc) {
    int t = blockIdx.x * blockDim.x + threadIdx.x;
    if (t >= TT) return;
    int s = (t < NE) ? esrc[t] : (t - NE);
    if (fenc(g_lk[t] + g_elk[t]) >= g_segscr[s]) {
        int slot = atomicAdd(&g_ncand, 1);
        g_cand[slot] = t;
        g_slot[t] = slot;
    }
}

// ------------------------- exact fp32 rescore of candidates -----------------
__global__ __launch_bounds__(256) void k_rescore(
    const float* __restrict__ W1, const float* __restrict__ b1,
    const float* __restrict__ Wlk, const float* __restrict__ blk,
    const int* __restrict__ esrc, const int* __restrict__ edst)
{
    const int c0 = blockIdx.x * 64;
    const int nc = g_ncand;
    if (c0 >= nc) return;

    __shared__ float Zs[32][68];
    __shared__ float Bs[32 * 256];
    __shared__ int s_src[64], s_dst[64], s_t[64];

    const int tid = threadIdx.x;
    const int cg = tid & 31, eg = tid >> 5;

    if (tid < 64) {
        int c = c0 + tid;
        int s = -1, d = -1, t = -1;
        if (c < nc) {
            t = g_cand[c];
            if (t < NE) { s = esrc[t]; d = edst[t]; }
            else        { s = t - NE; }
        }
        s_src[tid] = s; s_dst[tid] = d; s_t[tid] = t;
    }
    __syncthreads();

    float acc[8][8];
    #pragma unroll
    for (int i = 0; i < 8; i++)
        #pragma unroll
        for (int j = 0; j < 8; j++) acc[i][j] = 0.f;

    for (int k0 = 0; k0 < H0D; k0 += 32) {
        #pragma unroll
        for (int l = 0; l < 8; l++) {
            int idx = tid + l * 256;
            int e = idx >> 5, kk = idx & 31;
            int s = s_src[e];
            float v = 0.f;
            if (s >= 0) {
                v = g_A[(size_t)s * H0D + k0 + kk];
                int d = s_dst[e];
                if (d >= 0) v += g_B[(size_t)d * H0D + k0 + kk];
                v = fmaxf(v, 0.f);
            }
            Zs[kk][e] = v;
        }
        #pragma unroll
        for (int l = 0; l < 8; l++) {
            int idx4 = tid + l * 256;
            int kk = idx4 >> 6, c = (idx4 << 2) & 255;
            *(float4*)&Bs[kk * 256 + c] =
                *(const float4*)&W1[(size_t)(k0 + kk) * H1D + c];
        }
        __syncthreads();
        #pragma unroll
        for (int kk = 0; kk < 32; kk++) {
            float a[8], b[8];
            *(float4*)(a)     = *(const float4*)&Zs[kk][eg * 8];
            *(float4*)(a + 4) = *(const float4*)&Zs[kk][eg * 8 + 4];
            *(float4*)(b)     = *(const float4*)&Bs[kk * 256 + cg * 8];
            *(float4*)(b + 4) = *(const float4*)&Bs[kk * 256 + cg * 8 + 4];
            #pragma unroll
            for (int i = 0; i < 8; i++)
                #pragma unroll
                for (int j = 0; j < 8; j++)
                    acc[i][j] = fmaf(a[i], b[j], acc[i][j]);
        }
        __syncthreads();
    }

    float bb[8], wl[8];
    #pragma unroll
    for (int j = 0; j < 8; j++) {
        bb[j] = b1[cg * 8 + j];
        wl[j] = Wlk[cg * 8 + j];
    }

    float lkp[8];
    #pragma unroll
    for (int i = 0; i < 8; i++) {
        int e = eg * 8 + i;
        int c = c0 + e;
        float h[8];
        float p = 0.f;
        #pragma unroll
        for (int j = 0; j < 8; j++) {
            h[j] = fmaxf(acc[i][j] + bb[j], 0.f);
            p = fmaf(h[j], wl[j], p);
        }
        if (s_t[e] >= 0) {
            *(float4*)&g_h_cand[(size_t)c * H1D + cg * 8]     = *(float4*)h;
            *(float4*)&g_h_cand[(size_t)c * H1D + cg * 8 + 4] = *(float4*)(h + 4);
        }
        #pragma unroll
        for (int off = 16; off; off >>= 1)
            p += __shfl_xor_sync(0xffffffffu, p, off);
        lkp[i] = p;
    }

    if (cg == 0) {
        float lb = blk[0];
        #pragma unroll
        for (int i = 0; i < 8; i++) {
            int e = eg * 8 + i;
            int t = s_t[e];
            if (t >= 0) {
                float lk = lkp[i] + lb;
                unsigned long long key =
                    ((unsigned long long)fenc(lk) << 32) | (unsigned int)t;
                atomicMax(&g_seg2[s_src[e]], key);
            }
        }
    }
}

// ------------------------- winner decode + action head ----------------------
__global__ void k_final(const float* __restrict__ Wa, const float* __restrict__ ba,
                        const int* __restrict__ edst)
{
    int warp = (blockIdx.x * blockDim.x + threadIdx.x) >> 5;
    int lane = threadIdx.x & 31;
    if (warp >= NN) return;
    unsigned long long key = g_seg2[warp];
    int win = (int)(unsigned int)(key & 0xffffffffull);
    int chosen = (win < NE) ? edst[win] : -1;

    const float* h = &g_h_cand[(size_t)g_slot[win] * H1D];
    float s0 = 0.f, s1 = 0.f;
    #pragma unroll
    for (int j = 0; j < 8; j++) {
        float hv = h[lane + j * 32];
        s0 = fmaf(hv, Wa[(lane + j * 32) * 2 + 0], s0);
        s1 = fmaf(hv, Wa[(lane + j * 32) * 2 + 1], s1);
    }
    #pragma unroll
    for (int off = 16; off; off >>= 1) {
        s0 += __shfl_xor_sync(0xffffffffu, s0, off);
        s1 += __shfl_xor_sync(0xffffffffu, s1, off);
    }
    if (lane == 0) {
        float l0 = s0 + ba[0], l1 = s1 + ba[1];
        if (chosen >= 0 && (l1 > l0))
            atomicMax(&g_owner[chosen], warp);
    }
}

// ------------------------- recompute updated rows ---------------------------
__global__ __launch_bounds__(256) void k_newval(
    const float* __restrict__ feature, const float* __restrict__ We,
    const float* __restrict__ be, float* __restrict__ out)
{
    int t = blockIdx.x;
    int i = g_owner[t];
    if (i < 0) return;
    __shared__ float mf[FIN];
    int tid = threadIdx.x;
    for (int k = tid; k < FIN; k += 256)
        mf[k] = 0.5f * (feature[(size_t)i * FIN + k] + feature[(size_t)t * FIN + k]);
    __syncthreads();
    float acc = 0.f;
    #pragma unroll 8
    for (int k = 0; k < FIN; k++)
        acc = fmaf(mf[k], We[(size_t)k * ED + tid], acc);
    out[(size_t)t * ED + tid] = fmaxf(acc + be[tid], 0.f);
}

// ---------------------------------------------------------------------------
extern "C" void kernel_launch(void* const* d_in, const int* in_sizes, int n_in,
                              void* d_out, int out_size) {
    const float* feature = (const float*)d_in[0];
    const float* We      = (const float*)d_in[1];
    const float* be      = (const float*)d_in[2];
    const float* W0      = (const float*)d_in[3];
    const float* b0      = (const float*)d_in[4];
    const float* W1      = (const float*)d_in[5];
    const float* b1      = (const float*)d_in[6];
    const float* Wlk     = (const float*)d_in[7];
    const float* blk     = (const float*)d_in[8];
    const float* Wa      = (const float*)d_in[9];
    const float* ba      = (const float*)d_in[10];
    const int*   esrc    = (const int*)d_in[11];
    const int*   edst    = (const int*)d_in[12];
    float* out = (float*)d_out;

    static int smem_set = 0;
    if (!smem_set) {
        cudaFuncSetAttribute(k_screen,
                             cudaFuncAttributeMaxDynamicSharedMemorySize,
                             HMMA_SMEM);
        cudaFuncSetAttribute(k_hgemm,
                             cudaFuncAttributeMaxDynamicSharedMemorySize,
                             HMMA_SMEM);
        smem_set = 1;
    }

    k_init<<<(NN + 255) / 256, 256>>>();
    k_prepw<<<(H0D * H0D + 255) / 256, 256>>>(W1, We, W0);
    k_prepc<<<1, 256>>>(W1, Wlk);

    // emb = relu(feature @ We + be) -> out   (split-HMMA)
    k_hgemm<<<dim3(157, 1, 1), 256, HMMA_SMEM>>>(
        feature, FIN, NN, 16, /*bsel=*/0, /*zfuse=*/0, be, out, 0, ED, 1);
    // g_A = emb @ W0[:256,:] + b0 ; g_B = emb @ W0[256:,:]  (fused via z)
    k_hgemm<<<dim3(157, 2, 2), 256, HMMA_SMEM>>>(
        out, ED, NN, 8, /*bsel=*/1, /*zfuse=*/1, b0, nullptr, 1, H0D, 0);

    k_screen<<<(TT + 63) / 64, 256, HMMA_SMEM>>>(b1, Wlk, blk, esrc, edst);
    k_compact<<<(TT + 255) / 256, 256>>>(esrc);
    k_rescore<<<(TT + 63) / 64, 256>>>(W1, b1, Wlk, blk, esrc, edst);
    k_final<<<(NN * 32 + 255) / 256, 256>>>(Wa, ba, edst);
    k_newval<<<NN, 256>>>(feature, We, be, out);
}

// round 9
// speedup vs baseline: 2.2139x; 1.1525x over previous
#include <cuda_runtime.h>
#include <cuda_fp16.h>
#include <cstdint>

#define NN   10000
#define FIN  512
#define ED   256
#define H0D  512
#define H1D  256
#define NE   160000
#define TT   (NE + NN)

#define KCOEF 8e-5f
#define TINY  1.5e-3f

// ------------------------- device scratch (no allocs allowed) ---------------
__device__ float g_A[NN * H0D];
__device__ float g_B[NN * H0D];
__device__ __half g_W1h[H1D * H0D];
__device__ __half g_W1l[H1D * H0D];
__device__ __half g_Weh[ED * FIN];
__device__ __half g_Wel[ED * FIN];
__device__ __half g_W0h[H0D * H0D];
__device__ __half g_W0l[H0D * H0D];
__device__ float g_C;
__device__ float g_lk[TT];
__device__ float g_elk[TT];
__device__ unsigned int g_segscr[NN];
__device__ unsigned long long g_seg2[NN];
__device__ int g_owner[NN];
__device__ int g_ncand;
__device__ int g_cand[TT];
__device__ int g_slot[TT];
__device__ float g_h_cand[(size_t)TT * H1D];

__device__ __forceinline__ unsigned int fenc(float f) {
    unsigned int u = __float_as_uint(f);
    return (u & 0x80000000u) ? ~u : (u | 0x80000000u);
}
__device__ __forceinline__ uint32_t smem_u32(const void* p) {
    uint32_t a;
    asm("{ .reg .u64 t; cvta.to.shared.u64 t, %1; cvt.u32.u64 %0, t; }"
        : "=r"(a) : "l"(p));
    return a;
}
__device__ __forceinline__ void ldsm4(uint32_t& r0, uint32_t& r1,
                                      uint32_t& r2, uint32_t& r3, uint32_t a) {
    asm volatile("ldmatrix.sync.aligned.m8n8.x4.shared.b16 {%0,%1,%2,%3}, [%4];"
                 : "=r"(r0), "=r"(r1), "=r"(r2), "=r"(r3) : "r"(a));
}
__device__ __forceinline__ void mma16816(float* c, uint32_t a0, uint32_t a1,
                                         uint32_t a2, uint32_t a3,
                                         uint32_t b0, uint32_t b1) {
    asm volatile("mma.sync.aligned.m16n8k16.row.col.f32.f16.f16.f32 "
        "{%0,%1,%2,%3}, {%4,%5,%6,%7}, {%8,%9}, {%0,%1,%2,%3};"
        : "+f"(c[0]), "+f"(c[1]), "+f"(c[2]), "+f"(c[3])
        : "r"(a0), "r"(a1), "r"(a2), "r"(a3), "r"(b0), "r"(b1));
}
__device__ __forceinline__ void cp16(uint32_t s, const void* g) {
    asm volatile("cp.async.cg.shared.global [%0], [%1], 16;" :: "r"(s), "l"(g));
}
#define CP_COMMIT() asm volatile("cp.async.commit_group;" ::: "memory")
#define CP_WAIT0()  asm volatile("cp.async.wait_group 0;" ::: "memory")

// ------------------------- init ---------------------------------------------
__global__ void k_init() {
    int i = blockIdx.x * blockDim.x + threadIdx.x;
    if (i < NN) { g_segscr[i] = 0u; g_seg2[i] = 0ull; g_owner[i] = -1; }
    if (i == 0) g_ncand = 0;
}

// ------------------------- weight transpose + fp16 hi/lo splits -------------
__global__ void k_prepw(const float* __restrict__ W1,
                        const float* __restrict__ We,
                        const float* __restrict__ W0) {
    int idx = blockIdx.x * blockDim.x + threadIdx.x;
    if (idx < H1D * H0D) {
        int n = idx >> 9, k = idx & 511;
        float w = W1[(size_t)k * H1D + n];
        __half h = __float2half_rn(w);
        g_W1h[idx] = h;
        g_W1l[idx] = __float2half_rn(w - __half2float(h));
    }
    if (idx < ED * FIN) {
        int n = idx >> 9, k = idx & 511;
        float w = We[(size_t)k * ED + n];
        __half h = __float2half_rn(w);
        g_Weh[idx] = h;
        g_Wel[idx] = __float2half_rn(w - __half2float(h));
    }
    if (idx < H0D * H0D) {
        int n = idx >> 9, k = idx & 511;
        float w = W0[(size_t)k * H0D + n];
        __half h = __float2half_rn(w);
        g_W0h[idx] = h;
        g_W0l[idx] = __float2half_rn(w - __half2float(h));
    }
}

// ------------------------- C = sum_j ||W1_:j|| * |Wlk_j| --------------------
__global__ void k_prepc(const float* __restrict__ W1,
                        const float* __restrict__ Wlk) {
    __shared__ float red[256];
    int j = threadIdx.x;
    float s = 0.f;
    for (int k = 0; k < H0D; k++) {
        float w = W1[(size_t)k * H1D + j];
        s = fmaf(w, w, s);
    }
    red[j] = sqrtf(s) * fabsf(Wlk[j]);
    __syncthreads();
    for (int o = 128; o; o >>= 1) {
        if (j < o) red[j] += red[j + o];
        __syncthreads();
    }
    if (j == 0) g_C = red[0];
}

// ------------------------- shared HMMA tile constants -----------------------
#define ASTR 40
#define OFF_AH 0
#define OFF_AL 2560
#define OFF_BH 5120
#define OFF_BL 15360
#define BUF_HALF 25600
#define HMMA_SMEM (2 * BUF_HALF * 2)   // 102400 B: double-buffered

// ------------------------- pipelined split-HMMA GEMM ------------------------
__global__ void __launch_bounds__(256, 2)
k_hgemm(const float* __restrict__ A, int lda, int M, int nkb,
        int bsel, int zfuse, const float* __restrict__ bias,
        float* __restrict__ Cp, int csel0, int ldc, int do_relu)
{
    extern __shared__ __align__(16) __half smh[];
    __shared__ float s_bias[256];

    const int z = zfuse ? blockIdx.z : 0;
    const int csel = csel0 + z;
    const int koff = z * 256;
    float* C = (csel == 1) ? g_A : (csel == 2) ? g_B : Cp;
    const __half* BTh = bsel ? g_W0h : g_Weh;
    const __half* BTl = bsel ? g_W0l : g_Wel;
    const float* bias_eff = (csel == 2) ? nullptr : bias;

    const int tid = threadIdx.x, wid = tid >> 5, lane = tid & 31;
    const int wm = wid & 3, wn = wid >> 2;
    const int m0 = wm * 16;
    const int row0 = blockIdx.x * 64;
    const int n0 = blockIdx.y * 256;

    s_bias[tid] = bias_eff ? bias_eff[n0 + tid] : 0.f;

    const int ar = tid >> 2, kq = (tid & 3) * 8;
    const int grow = row0 + ar;
    const float4* pA = (const float4*)(A + (size_t)(grow < M ? grow : 0) * lda);

    const uint32_t sb = smem_u32(smh);
    const uint32_t aRow = m0 + (lane & 15);
    const uint32_t aCol = (lane < 16) ? 0 : 8;
    const uint32_t bRow0 = wn * 128 + (lane & 7) + ((lane >= 16) ? 8 : 0);
    const uint32_t bCol = (lane & 8) ? 8 : 0;

    float acc[16][4];
    #pragma unroll
    for (int i = 0; i < 16; i++)
        #pragma unroll
        for (int j = 0; j < 4; j++) acc[i][j] = 0.f;

    // --- staging helpers ----------------------------------------------------
    auto ldgA = [&](int kb, float4& r0, float4& r1) {
        int f4 = kb * 8 + (tid & 3) * 2;
        if (grow < M) { r0 = pA[f4]; r1 = pA[f4 + 1]; }
        else { r0 = make_float4(0.f,0.f,0.f,0.f); r1 = r0; }
    };
    auto stsA = [&](int buf, float4 a0, float4 a1) {
        float v[8] = {a0.x, a0.y, a0.z, a0.w, a1.x, a1.y, a1.z, a1.w};
        __half* dh = smh + buf * BUF_HALF + OFF_AH + ar * ASTR + kq;
        __half* dl = smh + buf * BUF_HALF + OFF_AL + ar * ASTR + kq;
        #pragma unroll
        for (int e = 0; e < 8; e++) {
            __half hh = __float2half_rn(v[e]);
            dh[e] = hh;
            dl[e] = __float2half_rn(v[e] - __half2float(hh));
        }
    };
    auto stageB = [&](int kb, int buf) {
        const __half* srcH = BTh + (size_t)(n0 + tid) * 512 + koff + kb * 32;
        const __half* srcL = BTl + (size_t)(n0 + tid) * 512 + koff + kb * 32;
        uint32_t dH = sb + (buf * BUF_HALF + OFF_BH + tid * ASTR) * 2;
        uint32_t dL = sb + (buf * BUF_HALF + OFF_BL + tid * ASTR) * 2;
        #pragma unroll
        for (int q = 0; q < 4; q++) {
            cp16(dH + q * 16, srcH + q * 8);
            cp16(dL + q * 16, srcL + q * 8);
        }
    };
    auto compute = [&](int buf) {
        const uint32_t base = sb + buf * BUF_HALF * 2;
        #pragma unroll
        for (int ks = 0; ks < 2; ks++) {
            const uint32_t kofs = ks * 16;
            uint32_t ah0, ah1, ah2, ah3, al0, al1, al2, al3;
            ldsm4(ah0, ah1, ah2, ah3, base + (OFF_AH + aRow * ASTR + aCol + kofs) * 2);
            ldsm4(al0, al1, al2, al3, base + (OFF_AL + aRow * ASTR + aCol + kofs) * 2);
            #pragma unroll
            for (int ntp = 0; ntp < 8; ntp++) {
                uint32_t brow = bRow0 + ntp * 16;
                uint32_t bh0, bh1, bh2, bh3, bl0, bl1, bl2, bl3;
                ldsm4(bh0, bh1, bh2, bh3, base + (OFF_BH + brow * ASTR + bCol + kofs) * 2);
                ldsm4(bl0, bl1, bl2, bl3, base + (OFF_BL + brow * ASTR + bCol + kofs) * 2);
                float* c0 = acc[ntp * 2];
                float* c1 = acc[ntp * 2 + 1];
                mma16816(c0, ah0, ah1, ah2, ah3, bh0, bh1);
                mma16816(c0, al0, al1, al2, al3, bh0, bh1);
                mma16816(c0, ah0, ah1, ah2, ah3, bl0, bl1);
                mma16816(c1, ah0, ah1, ah2, ah3, bh2, bh3);
                mma16816(c1, al0, al1, al2, al3, bh2, bh3);
                mma16816(c1, ah0, ah1, ah2, ah3, bl2, bl3);
            }
        }
    };

    // --- pipelined mainloop -------------------------------------------------
    float4 ra0, ra1;
    ldgA(0, ra0, ra1);
    stsA(0, ra0, ra1);
    stageB(0, 0); CP_COMMIT();
    if (nkb > 1) ldgA(1, ra0, ra1);
    CP_WAIT0();
    __syncthreads();

    for (int kb = 0; kb < nkb; kb++) {
        const int cur = kb & 1;
        if (kb + 1 < nkb) {
            stsA(cur ^ 1, ra0, ra1);
            stageB(kb + 1, cur ^ 1); CP_COMMIT();
            if (kb + 2 < nkb) ldgA(kb + 2, ra0, ra1);
        }
        compute(cur);
        if (kb + 1 < nkb) CP_WAIT0();
        __syncthreads();
    }

    // --- epilogue -----------------------------------------------------------
    const int g = lane >> 2, tg = lane & 3;
    const int r0 = row0 + m0 + g;
    const int r1 = r0 + 8;
    #pragma unroll
    for (int nt = 0; nt < 16; nt++) {
        int c = wn * 128 + nt * 8 + tg * 2;
        float b0v = s_bias[c], b1v = s_bias[c + 1];
        float v00 = acc[nt][0] + b0v, v01 = acc[nt][1] + b1v;
        float v10 = acc[nt][2] + b0v, v11 = acc[nt][3] + b1v;
        if (do_relu) {
            v00 = fmaxf(v00, 0.f); v01 = fmaxf(v01, 0.f);
            v10 = fmaxf(v10, 0.f); v11 = fmaxf(v11, 0.f);
        }
        if (r0 < M) *(float2*)&C[(size_t)r0 * ldc + n0 + c] = make_float2(v00, v01);
        if (r1 < M) *(float2*)&C[(size_t)r1 * ldc + n0 + c] = make_float2(v10, v11);
    }
}

// ------------------------- pipelined HMMA screening -------------------------
__global__ void __launch_bounds__(256, 2)
k_screen(const float* __restrict__ b1, const float* __restrict__ Wlk,
         const float* __restrict__ blk,
         const int* __restrict__ esrc, const int* __restrict__ edst)
{
    extern __shared__ __align__(16) __half smh[];
    __shared__ float s_n2[64];
    __shared__ float s_lk[2][64];
    __shared__ int s_src[64], s_dst[64];
    __shared__ float s_b1[256], s_wlk[256];

    const int tid = threadIdx.x, wid = tid >> 5, lane = tid & 31;
    const int wm = wid & 3, wn = wid >> 2;
    const int m0 = wm * 16;
    const int t0 = blockIdx.x * 64;

    if (tid < 64) {
        int t = t0 + tid;
        int s = -1, d = -1;
        if (t < TT) {
            if (t < NE) { s = esrc[t]; d = edst[t]; }
            else        { s = t - NE; }
        }
        s_src[tid] = s; s_dst[tid] = d;
        s_n2[tid] = 0.f;
    }
    s_b1[tid]  = b1[tid];
    s_wlk[tid] = Wlk[tid];
    __syncthreads();

    const int ar = tid >> 2, kq = (tid & 3) * 8;
    const int ss = s_src[ar], dd = s_dst[ar];
    const float4* pA = (const float4*)(g_A + (size_t)(ss < 0 ? 0 : ss) * H0D);
    const float4* pB = (const float4*)(g_B + (size_t)(dd < 0 ? 0 : dd) * H0D);

    const uint32_t sb = smem_u32(smh);
    const uint32_t aRow = m0 + (lane & 15);
    const uint32_t aCol = (lane < 16) ? 0 : 8;
    const uint32_t bRow0 = wn * 128 + (lane & 7) + ((lane >= 16) ? 8 : 0);
    const uint32_t bCol = (lane & 8) ? 8 : 0;

    float acc[16][4];
    #pragma unroll
    for (int i = 0; i < 16; i++)
        #pragma unroll
        for (int j = 0; j < 4; j++) acc[i][j] = 0.f;

    float n2acc = 0.f;

    auto ldgA = [&](int kb, float4* r) {
        int f4 = kb * 8 + (tid & 3) * 2;
        if (ss >= 0) {
            r[0] = pA[f4]; r[1] = pA[f4 + 1];
            if (dd >= 0) { r[2] = pB[f4]; r[3] = pB[f4 + 1]; }
            else { r[2] = make_float4(0.f,0.f,0.f,0.f); r[3] = r[2]; }
        } else {
            r[0] = make_float4(0.f,0.f,0.f,0.f);
            r[1] = r[0]; r[2] = r[0]; r[3] = r[0];
        }
    };
    auto stsA = [&](int buf, const float4* r) {
        float v[8] = {r[0].x + r[2].x, r[0].y + r[2].y,
                      r[0].z + r[2].z, r[0].w + r[2].w,
                      r[1].x + r[3].x, r[1].y + r[3].y,
                      r[1].z + r[3].z, r[1].w + r[3].w};
        __half* dh = smh + buf * BUF_HALF + OFF_AH + ar * ASTR + kq;
        __half* dl = smh + buf * BUF_HALF + OFF_AL + ar * ASTR + kq;
        #pragma unroll
        for (int e = 0; e < 8; e++) {
            float x = fmaxf(v[e], 0.f);
            __half hh = __float2half_rn(x);
            dh[e] = hh;
            dl[e] = __float2half_rn(x - __half2float(hh));
            n2acc = fmaf(x, x, n2acc);
        }
    };
    auto stageB = [&](int kb, int buf) {
        const __half* srcH = g_W1h + (size_t)tid * H0D + kb * 32;
        const __half* srcL = g_W1l + (size_t)tid * H0D + kb * 32;
        uint32_t dH = sb + (buf * BUF_HALF + OFF_BH + tid * ASTR) * 2;
        uint32_t dL = sb + (buf * BUF_HALF + OFF_BL + tid * ASTR) * 2;
        #pragma unroll
        for (int q = 0; q < 4; q++) {
            cp16(dH + q * 16, srcH + q * 8);
            cp16(dL + q * 16, srcL + q * 8);
        }
    };
    auto compute = [&](int buf) {
        const uint32_t base = sb + buf * BUF_HALF * 2;
        #pragma unroll
        for (int ks = 0; ks < 2; ks++) {
            const uint32_t kofs = ks * 16;
            uint32_t ah0, ah1, ah2, ah3, al0, al1, al2, al3;
            ldsm4(ah0, ah1, ah2, ah3, base + (OFF_AH + aRow * ASTR + aCol + kofs) * 2);
            ldsm4(al0, al1, al2, al3, base + (OFF_AL + aRow * ASTR + aCol + kofs) * 2);
            #pragma unroll
            for (int ntp = 0; ntp < 8; ntp++) {
                uint32_t brow = bRow0 + ntp * 16;
                uint32_t bh0, bh1, bh2, bh3, bl0, bl1, bl2, bl3;
                ldsm4(bh0, bh1, bh2, bh3, base + (OFF_BH + brow * ASTR + bCol + kofs) * 2);
                ldsm4(bl0, bl1, bl2, bl3, base + (OFF_BL + brow * ASTR + bCol + kofs) * 2);
                float* c0 = acc[ntp * 2];
                float* c1 = acc[ntp * 2 + 1];
                mma16816(c0, ah0, ah1, ah2, ah3, bh0, bh1);
                mma16816(c0, al0, al1, al2, al3, bh0, bh1);
                mma16816(c0, ah0, ah1, ah2, ah3, bl0, bl1);
                mma16816(c1, ah0, ah1, ah2, ah3, bh2, bh3);
                mma16816(c1, al0, al1, al2, al3, bh2, bh3);
                mma16816(c1, ah0, ah1, ah2, ah3, bl2, bl3);
            }
        }
    };

    // --- pipelined mainloop (nkb = 16) --------------------------------------
    float4 ra[4];
    ldgA(0, ra);
    stsA(0, ra);
    stageB(0, 0); CP_COMMIT();
    ldgA(1, ra);
    CP_WAIT0();
    __syncthreads();

    const int nkb = 16;
    for (int kb = 0; kb < nkb; kb++) {
        const int cur = kb & 1;
        if (kb + 1 < nkb) {
            stsA(cur ^ 1, ra);
            stageB(kb + 1, cur ^ 1); CP_COMMIT();
            if (kb + 2 < nkb) ldgA(kb + 2, ra);
        }
        compute(cur);
        if (kb + 1 < nkb) CP_WAIT0();
        __syncthreads();
    }

    if (ss >= 0) atomicAdd(&s_n2[ar], n2acc);
    __syncthreads();

    // --- epilogue: lk = sum_j relu(P + b1_j) * wlk_j ------------------------
    const int g = lane >> 2, tg = lane & 3;
    float sum0 = 0.f, sum1 = 0.f;
    #pragma unroll
    for (int nt = 0; nt < 16; nt++) {
        int c0 = wn * 128 + nt * 8 + tg * 2;
        float b10 = s_b1[c0],     w0 = s_wlk[c0];
        float b11 = s_b1[c0 + 1], w1 = s_wlk[c0 + 1];
        sum0 += fmaxf(acc[nt][0] + b10, 0.f) * w0 +
                fmaxf(acc[nt][1] + b11, 0.f) * w1;
        sum1 += fmaxf(acc[nt][2] + b10, 0.f) * w0 +
                fmaxf(acc[nt][3] + b11, 0.f) * w1;
    }
    sum0 += __shfl_xor_sync(0xffffffffu, sum0, 1);
    sum0 += __shfl_xor_sync(0xffffffffu, sum0, 2);
    sum1 += __shfl_xor_sync(0xffffffffu, sum1, 1);
    sum1 += __shfl_xor_sync(0xffffffffu, sum1, 2);
    if (tg == 0) {
        s_lk[wn][m0 + g]     = sum0;
        s_lk[wn][m0 + g + 8] = sum1;
    }
    __syncthreads();

    if (tid < 64) {
        int t = t0 + tid;
        if (t < TT) {
            float lk = s_lk[0][tid] + s_lk[1][tid] + blk[0];
            float err = KCOEF * g_C * sqrtf(s_n2[tid]) + TINY;
            g_lk[t] = lk;
            g_elk[t] = err;
            atomicMax(&g_segscr[s_src[tid]], fenc(lk - err));
        }
    }
}

// ------------------------- candidate compaction -----------------------------
__global__ void k_compact(const int* __restrict__ esrc) {
    int t = blockIdx.x * blockDim.x + threadIdx.x;
    if (t >= TT) return;
    int s = (t < NE) ? esrc[t] : (t - NE);
    if (fenc(g_lk[t] + g_elk[t]) >= g_segscr[s]) {
        int slot = atomicAdd(&g_ncand, 1);
        g_cand[slot] = t;
        g_slot[t] = slot;
    }
}

// ------------------------- exact fp32 rescore of candidates -----------------
__global__ __launch_bounds__(256) void k_rescore(
    const float* __restrict__ W1, const float* __restrict__ b1,
    const float* __restrict__ Wlk, const float* __restrict__ blk,
    const int* __restrict__ esrc, const int* __restrict__ edst)
{
    const int c0 = blockIdx.x * 64;
    const int nc = g_ncand;
    if (c0 >= nc) return;

    __shared__ float Zs[32][68];
    __shared__ float Bs[32 * 256];
    __shared__ int s_src[64], s_dst[64], s_t[64];

    const int tid = threadIdx.x;
    const int cg = tid & 31, eg = tid >> 5;

    if (tid < 64) {
        int c = c0 + tid;
        int s = -1, d = -1, t = -1;
        if (c < nc) {
            t = g_cand[c];
            if (t < NE) { s = esrc[t]; d = edst[t]; }
            else        { s = t - NE; }
        }
        s_src[tid] = s; s_dst[tid] = d; s_t[tid] = t;
    }
    __syncthreads();

    float acc[8][8];
    #pragma unroll
    for (int i = 0; i < 8; i++)
        #pragma unroll
        for (int j = 0; j < 8; j++) acc[i][j] = 0.f;

    for (int k0 = 0; k0 < H0D; k0 += 32) {
        #pragma unroll
        for (int l = 0; l < 8; l++) {
            int idx = tid + l * 256;
            int e = idx >> 5, kk = idx & 31;
            int s = s_src[e];
            float v = 0.f;
            if (s >= 0) {
                v = g_A[(size_t)s * H0D + k0 + kk];
                int d = s_dst[e];
                if (d >= 0) v += g_B[(size_t)d * H0D + k0 + kk];
                v = fmaxf(v, 0.f);
            }
            Zs[kk][e] = v;
        }
        #pragma unroll
        for (int l = 0; l < 8; l++) {
            int idx4 = tid + l * 256;
            int kk = idx4 >> 6, c = (idx4 << 2) & 255;
            *(float4*)&Bs[kk * 256 + c] =
                *(const float4*)&W1[(size_t)(k0 + kk) * H1D + c];
        }
        __syncthreads();
        #pragma unroll
        for (int kk = 0; kk < 32; kk++) {
            float a[8], b[8];
            *(float4*)(a)     = *(const float4*)&Zs[kk][eg * 8];
            *(float4*)(a + 4) = *(const float4*)&Zs[kk][eg * 8 + 4];
            *(float4*)(b)     = *(const float4*)&Bs[kk * 256 + cg * 8];
            *(float4*)(b + 4) = *(const float4*)&Bs[kk * 256 + cg * 8 + 4];
            #pragma unroll
            for (int i = 0; i < 8; i++)
                #pragma unroll
                for (int j = 0; j < 8; j++)
                    acc[i][j] = fmaf(a[i], b[j], acc[i][j]);
        }
        __syncthreads();
    }

    float bb[8], wl[8];
    #pragma unroll
    for (int j = 0; j < 8; j++) {
        bb[j] = b1[cg * 8 + j];
        wl[j] = Wlk[cg * 8 + j];
    }

    float lkp[8];
    #pragma unroll
    for (int i = 0; i < 8; i++) {
        int e = eg * 8 + i;
        int c = c0 + e;
        float h[8];
        float p = 0.f;
        #pragma unroll
        for (int j = 0; j < 8; j++) {
            h[j] = fmaxf(acc[i][j] + bb[j], 0.f);
            p = fmaf(h[j], wl[j], p);
        }
        if (s_t[e] >= 0) {
            *(float4*)&g_h_cand[(size_t)c * H1D + cg * 8]     = *(float4*)h;
            *(float4*)&g_h_cand[(size_t)c * H1D + cg * 8 + 4] = *(float4*)(h + 4);
        }
        #pragma unroll
        for (int off = 16; off; off >>= 1)
            p += __shfl_xor_sync(0xffffffffu, p, off);
        lkp[i] = p;
    }

    if (cg == 0) {
        float lb = blk[0];
        #pragma unroll
        for (int i = 0; i < 8; i++) {
            int e = eg * 8 + i;
            int t = s_t[e];
            if (t >= 0) {
                float lk = lkp[i] + lb;
                unsigned long long key =
                    ((unsigned long long)fenc(lk) << 32) | (unsigned int)t;
                atomicMax(&g_seg2[s_src[e]], key);
            }
        }
    }
}

// ------------------------- winner decode + action head ----------------------
__global__ void k_final(const float* __restrict__ Wa, const float* __restrict__ ba,
                        const int* __restrict__ edst)
{
    int warp = (blockIdx.x * blockDim.x + threadIdx.x) >> 5;
    int lane = threadIdx.x & 31;
    if (warp >= NN) return;
    unsigned long long key = g_seg2[warp];
    int win = (int)(unsigned int)(key & 0xffffffffull);
    int chosen = (win < NE) ? edst[win] : -1;

    const float* h = &g_h_cand[(size_t)g_slot[win] * H1D];
    float s0 = 0.f, s1 = 0.f;
    #pragma unroll
    for (int j = 0; j < 8; j++) {
        float hv = h[lane + j * 32];
        s0 = fmaf(hv, Wa[(lane + j * 32) * 2 + 0], s0);
        s1 = fmaf(hv, Wa[(lane + j * 32) * 2 + 1], s1);
    }
    #pragma unroll
    for (int off = 16; off; off >>= 1) {
        s0 += __shfl_xor_sync(0xffffffffu, s0, off);
        s1 += __shfl_xor_sync(0xffffffffu, s1, off);
    }
    if (lane == 0) {
        float l0 = s0 + ba[0], l1 = s1 + ba[1];
        if (chosen >= 0 && (l1 > l0))
            atomicMax(&g_owner[chosen], warp);
    }
}

// ------------------------- recompute updated rows ---------------------------
__global__ __launch_bounds__(256) void k_newval(
    const float* __restrict__ feature, const float* __restrict__ We,
    const float* __restrict__ be, float* __restrict__ out)
{
    int t = blockIdx.x;
    int i = g_owner[t];
    if (i < 0) return;
    __shared__ float mf[FIN];
    int tid = threadIdx.x;
    for (int k = tid; k < FIN; k += 256)
        mf[k] = 0.5f * (feature[(size_t)i * FIN + k] + feature[(size_t)t * FIN + k]);
    __syncthreads();
    float acc = 0.f;
    #pragma unroll 8
    for (int k = 0; k < FIN; k++)
        acc = fmaf(mf[k], We[(size_t)k * ED + tid], acc);
    out[(size_t)t * ED + tid] = fmaxf(acc + be[tid], 0.f);
}

// ---------------------------------------------------------------------------
extern "C" void kernel_launch(void* const* d_in, const int* in_sizes, int n_in,
                              void* d_out, int out_size) {
    const float* feature = (const float*)d_in[0];
    const float* We      = (const float*)d_in[1];
    const float* be      = (const float*)d_in[2];
    const float* W0      = (const float*)d_in[3];
    const float* b0      = (const float*)d_in[4];
    const float* W1      = (const float*)d_in[5];
    const float* b1      = (const float*)d_in[6];
    const float* Wlk     = (const float*)d_in[7];
    const float* blk     = (const float*)d_in[8];
    const float* Wa      = (const float*)d_in[9];
    const float* ba      = (const float*)d_in[10];
    const int*   esrc    = (const int*)d_in[11];
    const int*   edst    = (const int*)d_in[12];
    float* out = (float*)d_out;

    static int smem_set = 0;
    if (!smem_set) {
        cudaFuncSetAttribute(k_screen,
                             cudaFuncAttributeMaxDynamicSharedMemorySize,
                             HMMA_SMEM);
        cudaFuncSetAttribute(k_hgemm,
                             cudaFuncAttributeMaxDynamicSharedMemorySize,
                             HMMA_SMEM);
        smem_set = 1;
    }

    k_init<<<(NN + 255) / 256, 256>>>();
    k_prepw<<<(H0D * H0D + 255) / 256, 256>>>(W1, We, W0);
    k_prepc<<<1, 256>>>(W1, Wlk);

    // emb = relu(feature @ We + be) -> out   (pipelined split-HMMA)
    k_hgemm<<<dim3(157, 1, 1), 256, HMMA_SMEM>>>(
        feature, FIN, NN, 16, 0, 0, be, out, 0, ED, 1);
    // g_A = emb @ W0[:256,:] + b0 ; g_B = emb @ W0[256:,:]  (fused via z)
    k_hgemm<<<dim3(157, 2, 2), 256, HMMA_SMEM>>>(
        out, ED, NN, 8, 1, 1, b0, nullptr, 1, H0D, 0);

    k_screen<<<(TT + 63) / 64, 256, HMMA_SMEM>>>(b1, Wlk, blk, esrc, edst);
    k_compact<<<(TT + 255) / 256, 256>>>(esrc);
    k_rescore<<<(TT + 63) / 64, 256>>>(W1, b1, Wlk, blk, esrc, edst);
    k_final<<<(NN * 32 + 255) / 256, 256>>>(Wa, ba, edst);
    k_newval<<<NN, 256>>>(feature, We, be, out);
}

// round 10
// speedup vs baseline: 2.2311x; 1.0078x over previous
#include <cuda_runtime.h>
#include <cuda_fp16.h>
#include <cstdint>

#define NN   10000
#define FIN  512
#define ED   256
#define H0D  512
#define H1D  256
#define NE   160000
#define TT   (NE + NN)

#define KCOEF 8e-5f
#define TINY  1.5e-3f

// ------------------------- device scratch (no allocs allowed) ---------------
__device__ float g_A[NN * H0D];
__device__ float g_B[NN * H0D];
__device__ __half g_W1h[H1D * H0D];
__device__ __half g_W1l[H1D * H0D];
__device__ __half g_Weh[ED * FIN];
__device__ __half g_Wel[ED * FIN];
__device__ __half g_W0h[H0D * H0D];
__device__ __half g_W0l[H0D * H0D];
__device__ float g_C;
__device__ float g_lk[TT];
__device__ float g_elk[TT];
__device__ unsigned int g_segscr[NN];
__device__ unsigned long long g_seg2[NN];
__device__ int g_owner[NN];
__device__ int g_ncand;
__device__ int g_cand[TT];
__device__ int g_slot[TT];
__device__ float g_h_cand[(size_t)TT * H1D];

__device__ __forceinline__ unsigned int fenc(float f) {
    unsigned int u = __float_as_uint(f);
    return (u & 0x80000000u) ? ~u : (u | 0x80000000u);
}
__device__ __forceinline__ uint32_t smem_u32(const void* p) {
    uint32_t a;
    asm("{ .reg .u64 t; cvta.to.shared.u64 t, %1; cvt.u32.u64 %0, t; }"
        : "=r"(a) : "l"(p));
    return a;
}
__device__ __forceinline__ void ldsm4(uint32_t& r0, uint32_t& r1,
                                      uint32_t& r2, uint32_t& r3, uint32_t a) {
    asm volatile("ldmatrix.sync.aligned.m8n8.x4.shared.b16 {%0,%1,%2,%3}, [%4];"
                 : "=r"(r0), "=r"(r1), "=r"(r2), "=r"(r3) : "r"(a));
}
__device__ __forceinline__ void mma16816(float* c, uint32_t a0, uint32_t a1,
                                         uint32_t a2, uint32_t a3,
                                         uint32_t b0, uint32_t b1) {
    asm volatile("mma.sync.aligned.m16n8k16.row.col.f32.f16.f16.f32 "
        "{%0,%1,%2,%3}, {%4,%5,%6,%7}, {%8,%9}, {%0,%1,%2,%3};"
        : "+f"(c[0]), "+f"(c[1]), "+f"(c[2]), "+f"(c[3])
        : "r"(a0), "r"(a1), "r"(a2), "r"(a3), "r"(b0), "r"(b1));
}
__device__ __forceinline__ void cp16(uint32_t s, const void* g) {
    asm volatile("cp.async.cg.shared.global [%0], [%1], 16;" :: "r"(s), "l"(g));
}
#define CP_COMMIT() asm volatile("cp.async.commit_group;" ::: "memory")
#define CP_WAIT0()  asm volatile("cp.async.wait_group 0;" ::: "memory")

// ------------------------- init ---------------------------------------------
__global__ void k_init() {
    int i = blockIdx.x * blockDim.x + threadIdx.x;
    if (i < NN) { g_segscr[i] = 0u; g_seg2[i] = 0ull; g_owner[i] = -1; }
    if (i == 0) g_ncand = 0;
}

// ------------------------- weight transpose + fp16 hi/lo splits -------------
__global__ void k_prepw(const float* __restrict__ W1,
                        const float* __restrict__ We,
                        const float* __restrict__ W0) {
    int idx = blockIdx.x * blockDim.x + threadIdx.x;
    if (idx < H1D * H0D) {
        int n = idx >> 9, k = idx & 511;
        float w = W1[(size_t)k * H1D + n];
        __half h = __float2half_rn(w);
        g_W1h[idx] = h;
        g_W1l[idx] = __float2half_rn(w - __half2float(h));
    }
    if (idx < ED * FIN) {
        int n = idx >> 9, k = idx & 511;
        float w = We[(size_t)k * ED + n];
        __half h = __float2half_rn(w);
        g_Weh[idx] = h;
        g_Wel[idx] = __float2half_rn(w - __half2float(h));
    }
    if (idx < H0D * H0D) {
        int n = idx >> 9, k = idx & 511;
        float w = W0[(size_t)k * H0D + n];
        __half h = __float2half_rn(w);
        g_W0h[idx] = h;
        g_W0l[idx] = __float2half_rn(w - __half2float(h));
    }
}

// ------------------------- C = sum_j ||W1_:j|| * |Wlk_j| --------------------
__global__ void k_prepc(const float* __restrict__ W1,
                        const float* __restrict__ Wlk) {
    __shared__ float red[256];
    int j = threadIdx.x;
    float s = 0.f;
    for (int k = 0; k < H0D; k++) {
        float w = W1[(size_t)k * H1D + j];
        s = fmaf(w, w, s);
    }
    red[j] = sqrtf(s) * fabsf(Wlk[j]);
    __syncthreads();
    for (int o = 128; o; o >>= 1) {
        if (j < o) red[j] += red[j + o];
        __syncthreads();
    }
    if (j == 0) g_C = red[0];
}

// ------------------------- shared HMMA tile constants -----------------------
#define ASTR 40
#define OFF_AH 0
#define OFF_AL 2560
#define OFF_BH 5120
#define OFF_BL 15360
#define BUF_HALF 25600
#define HMMA_SMEM (2 * BUF_HALF * 2)

// Interleaved-accumulator compute phase (shared by k_hgemm / k_screen).
// Pairs of ntp tiles; 12 mmas per pair ordered so same-acc reuse distance = 4.
#define COMPUTE_PHASE(base)                                                    \
    _Pragma("unroll")                                                          \
    for (int ks = 0; ks < 2; ks++) {                                           \
        const uint32_t kofs = ks * 16;                                         \
        uint32_t ah0, ah1, ah2, ah3, al0, al1, al2, al3;                       \
        ldsm4(ah0, ah1, ah2, ah3, (base) + (OFF_AH + aRow * ASTR + aCol + kofs) * 2); \
        ldsm4(al0, al1, al2, al3, (base) + (OFF_AL + aRow * ASTR + aCol + kofs) * 2); \
        _Pragma("unroll")                                                      \
        for (int np = 0; np < 4; np++) {                                       \
            uint32_t brow_e = bRow0 + (2 * np) * 16;                           \
            uint32_t brow_o = brow_e + 16;                                     \
            uint32_t eh0, eh1, eh2, eh3, el0, el1, el2, el3;                   \
            uint32_t oh0, oh1, oh2, oh3, ol0, ol1, ol2, ol3;                   \
            ldsm4(eh0, eh1, eh2, eh3, (base) + (OFF_BH + brow_e * ASTR + bCol + kofs) * 2); \
            ldsm4(el0, el1, el2, el3, (base) + (OFF_BL + brow_e * ASTR + bCol + kofs) * 2); \
            ldsm4(oh0, oh1, oh2, oh3, (base) + (OFF_BH + brow_o * ASTR + bCol + kofs) * 2); \
            ldsm4(ol0, ol1, ol2, ol3, (base) + (OFF_BL + brow_o * ASTR + bCol + kofs) * 2); \
            float* c0e = acc[4 * np + 0];                                      \
            float* c1e = acc[4 * np + 1];                                      \
            float* c0o = acc[4 * np + 2];                                      \
            float* c1o = acc[4 * np + 3];                                      \
            mma16816(c0e, ah0, ah1, ah2, ah3, eh0, eh1);                       \
            mma16816(c1e, ah0, ah1, ah2, ah3, eh2, eh3);                       \
            mma16816(c0o, ah0, ah1, ah2, ah3, oh0, oh1);                       \
            mma16816(c1o, ah0, ah1, ah2, ah3, oh2, oh3);                       \
            mma16816(c0e, al0, al1, al2, al3, eh0, eh1);                       \
            mma16816(c1e, al0, al1, al2, al3, eh2, eh3);                       \
            mma16816(c0o, al0, al1, al2, al3, oh0, oh1);                       \
            mma16816(c1o, al0, al1, al2, al3, oh2, oh3);                       \
            mma16816(c0e, ah0, ah1, ah2, ah3, el0, el1);                       \
            mma16816(c1e, ah0, ah1, ah2, ah3, el2, el3);                       \
            mma16816(c0o, ah0, ah1, ah2, ah3, ol0, ol1);                       \
            mma16816(c1o, ah0, ah1, ah2, ah3, ol2, ol3);                       \
        }                                                                      \
    }

// ------------------------- pipelined split-HMMA GEMM ------------------------
__global__ void __launch_bounds__(256, 2)
k_hgemm(const float* __restrict__ A, int lda, int M, int nkb,
        int bsel, int zfuse, const float* __restrict__ bias,
        float* __restrict__ Cp, int csel0, int ldc, int do_relu)
{
    extern __shared__ __align__(16) __half smh[];
    __shared__ float s_bias[256];

    const int z = zfuse ? blockIdx.z : 0;
    const int csel = csel0 + z;
    const int koff = z * 256;
    float* C = (csel == 1) ? g_A : (csel == 2) ? g_B : Cp;
    const __half* BTh = bsel ? g_W0h : g_Weh;
    const __half* BTl = bsel ? g_W0l : g_Wel;
    const float* bias_eff = (csel == 2) ? nullptr : bias;

    const int tid = threadIdx.x, wid = tid >> 5, lane = tid & 31;
    const int wm = wid & 3, wn = wid >> 2;
    const int m0 = wm * 16;
    const int row0 = blockIdx.x * 64;
    const int n0 = blockIdx.y * 256;

    s_bias[tid] = bias_eff ? bias_eff[n0 + tid] : 0.f;

    const int ar = tid >> 2, kq = (tid & 3) * 8;
    const int grow = row0 + ar;
    const float4* pA = (const float4*)(A + (size_t)(grow < M ? grow : 0) * lda);

    const uint32_t sb = smem_u32(smh);
    const uint32_t aRow = m0 + (lane & 15);
    const uint32_t aCol = (lane < 16) ? 0 : 8;
    const uint32_t bRow0 = wn * 128 + (lane & 7) + ((lane >= 16) ? 8 : 0);
    const uint32_t bCol = (lane & 8) ? 8 : 0;

    float acc[16][4];
    #pragma unroll
    for (int i = 0; i < 16; i++)
        #pragma unroll
        for (int j = 0; j < 4; j++) acc[i][j] = 0.f;

    auto ldgA = [&](int kb, float4& r0, float4& r1) {
        int f4 = kb * 8 + (tid & 3) * 2;
        if (grow < M) { r0 = pA[f4]; r1 = pA[f4 + 1]; }
        else { r0 = make_float4(0.f,0.f,0.f,0.f); r1 = r0; }
    };
    auto stsA = [&](int buf, float4 a0, float4 a1) {
        float v[8] = {a0.x, a0.y, a0.z, a0.w, a1.x, a1.y, a1.z, a1.w};
        __half* dh = smh + buf * BUF_HALF + OFF_AH + ar * ASTR + kq;
        __half* dl = smh + buf * BUF_HALF + OFF_AL + ar * ASTR + kq;
        #pragma unroll
        for (int e = 0; e < 8; e++) {
            __half hh = __float2half_rn(v[e]);
            dh[e] = hh;
            dl[e] = __float2half_rn(v[e] - __half2float(hh));
        }
    };
    auto stageB = [&](int kb, int buf) {
        const __half* srcH = BTh + (size_t)(n0 + tid) * 512 + koff + kb * 32;
        const __half* srcL = BTl + (size_t)(n0 + tid) * 512 + koff + kb * 32;
        uint32_t dH = sb + (buf * BUF_HALF + OFF_BH + tid * ASTR) * 2;
        uint32_t dL = sb + (buf * BUF_HALF + OFF_BL + tid * ASTR) * 2;
        #pragma unroll
        for (int q = 0; q < 4; q++) {
            cp16(dH + q * 16, srcH + q * 8);
            cp16(dL + q * 16, srcL + q * 8);
        }
    };

    float4 ra0, ra1;
    ldgA(0, ra0, ra1);
    stsA(0, ra0, ra1);
    stageB(0, 0); CP_COMMIT();
    if (nkb > 1) ldgA(1, ra0, ra1);
    CP_WAIT0();
    __syncthreads();

    for (int kb = 0; kb < nkb; kb++) {
        const int cur = kb & 1;
        if (kb + 1 < nkb) {
            stsA(cur ^ 1, ra0, ra1);
            stageB(kb + 1, cur ^ 1); CP_COMMIT();
            if (kb + 2 < nkb) ldgA(kb + 2, ra0, ra1);
        }
        {
            const uint32_t cbase = sb + cur * BUF_HALF * 2;
            COMPUTE_PHASE(cbase)
        }
        if (kb + 1 < nkb) CP_WAIT0();
        __syncthreads();
    }

    const int g = lane >> 2, tg = lane & 3;
    const int r0 = row0 + m0 + g;
    const int r1 = r0 + 8;
    #pragma unroll
    for (int nt = 0; nt < 16; nt++) {
        int c = wn * 128 + nt * 8 + tg * 2;
        float b0v = s_bias[c], b1v = s_bias[c + 1];
        float v00 = acc[nt][0] + b0v, v01 = acc[nt][1] + b1v;
        float v10 = acc[nt][2] + b0v, v11 = acc[nt][3] + b1v;
        if (do_relu) {
            v00 = fmaxf(v00, 0.f); v01 = fmaxf(v01, 0.f);
            v10 = fmaxf(v10, 0.f); v11 = fmaxf(v11, 0.f);
        }
        if (r0 < M) *(float2*)&C[(size_t)r0 * ldc + n0 + c] = make_float2(v00, v01);
        if (r1 < M) *(float2*)&C[(size_t)r1 * ldc + n0 + c] = make_float2(v10, v11);
    }
}

// ------------------------- pipelined HMMA screening -------------------------
__global__ void __launch_bounds__(256, 2)
k_screen(const float* __restrict__ b1, const float* __restrict__ Wlk,
         const float* __restrict__ blk,
         const int* __restrict__ esrc, const int* __restrict__ edst)
{
    extern __shared__ __align__(16) __half smh[];
    __shared__ float s_n2[64];
    __shared__ float s_lk[2][64];
    __shared__ int s_src[64], s_dst[64];
    __shared__ float s_b1[256], s_wlk[256];

    const int tid = threadIdx.x, wid = tid >> 5, lane = tid & 31;
    const int wm = wid & 3, wn = wid >> 2;
    const int m0 = wm * 16;
    const int t0 = blockIdx.x * 64;

    if (tid < 64) {
        int t = t0 + tid;
        int s = -1, d = -1;
        if (t < TT) {
            if (t < NE) { s = esrc[t]; d = edst[t]; }
            else        { s = t - NE; }
        }
        s_src[tid] = s; s_dst[tid] = d;
        s_n2[tid] = 0.f;
    }
    s_b1[tid]  = b1[tid];
    s_wlk[tid] = Wlk[tid];
    __syncthreads();

    const int ar = tid >> 2, kq = (tid & 3) * 8;
    const int ss = s_src[ar], dd = s_dst[ar];
    const float4* pA = (const float4*)(g_A + (size_t)(ss < 0 ? 0 : ss) * H0D);
    const float4* pB = (const float4*)(g_B + (size_t)(dd < 0 ? 0 : dd) * H0D);

    const uint32_t sb = smem_u32(smh);
    const uint32_t aRow = m0 + (lane & 15);
    const uint32_t aCol = (lane < 16) ? 0 : 8;
    const uint32_t bRow0 = wn * 128 + (lane & 7) + ((lane >= 16) ? 8 : 0);
    const uint32_t bCol = (lane & 8) ? 8 : 0;

    float acc[16][4];
    #pragma unroll
    for (int i = 0; i < 16; i++)
        #pragma unroll
        for (int j = 0; j < 4; j++) acc[i][j] = 0.f;

    float n2acc = 0.f;

    auto ldgA = [&](int kb, float4* r) {
        int f4 = kb * 8 + (tid & 3) * 2;
        if (ss >= 0) {
            r[0] = pA[f4]; r[1] = pA[f4 + 1];
            if (dd >= 0) { r[2] = pB[f4]; r[3] = pB[f4 + 1]; }
            else { r[2] = make_float4(0.f,0.f,0.f,0.f); r[3] = r[2]; }
        } else {
            r[0] = make_float4(0.f,0.f,0.f,0.f);
            r[1] = r[0]; r[2] = r[0]; r[3] = r[0];
        }
    };
    auto stsA = [&](int buf, const float4* r) {
        float v[8] = {r[0].x + r[2].x, r[0].y + r[2].y,
                      r[0].z + r[2].z, r[0].w + r[2].w,
                      r[1].x + r[3].x, r[1].y + r[3].y,
                      r[1].z + r[3].z, r[1].w + r[3].w};
        __half* dh = smh + buf * BUF_HALF + OFF_AH + ar * ASTR + kq;
        __half* dl = smh + buf * BUF_HALF + OFF_AL + ar * ASTR + kq;
        #pragma unroll
        for (int e = 0; e < 8; e++) {
            float x = fmaxf(v[e], 0.f);
            __half hh = __float2half_rn(x);
            dh[e] = hh;
            dl[e] = __float2half_rn(x - __half2float(hh));
            n2acc = fmaf(x, x, n2acc);
        }
    };
    auto stageB = [&](int kb, int buf) {
        const __half* srcH = g_W1h + (size_t)tid * H0D + kb * 32;
        const __half* srcL = g_W1l + (size_t)tid * H0D + kb * 32;
        uint32_t dH = sb + (buf * BUF_HALF + OFF_BH + tid * ASTR) * 2;
        uint32_t dL = sb + (buf * BUF_HALF + OFF_BL + tid * ASTR) * 2;
        #pragma unroll
        for (int q = 0; q < 4; q++) {
            cp16(dH + q * 16, srcH + q * 8);
            cp16(dL + q * 16, srcL + q * 8);
        }
    };

    float4 ra[4];
    ldgA(0, ra);
    stsA(0, ra);
    stageB(0, 0); CP_COMMIT();
    ldgA(1, ra);
    CP_WAIT0();
    __syncthreads();

    const int nkb = 16;
    for (int kb = 0; kb < nkb; kb++) {
        const int cur = kb & 1;
        if (kb + 1 < nkb) {
            stsA(cur ^ 1, ra);
            stageB(kb + 1, cur ^ 1); CP_COMMIT();
            if (kb + 2 < nkb) ldgA(kb + 2, ra);
        }
        {
            const uint32_t cbase = sb + cur * BUF_HALF * 2;
            COMPUTE_PHASE(cbase)
        }
        if (kb + 1 < nkb) CP_WAIT0();
        __syncthreads();
    }

    if (ss >= 0) atomicAdd(&s_n2[ar], n2acc);
    __syncthreads();

    const int g = lane >> 2, tg = lane & 3;
    float sum0 = 0.f, sum1 = 0.f;
    #pragma unroll
    for (int nt = 0; nt < 16; nt++) {
        int c0 = wn * 128 + nt * 8 + tg * 2;
        float b10 = s_b1[c0],     w0 = s_wlk[c0];
        float b11 = s_b1[c0 + 1], w1 = s_wlk[c0 + 1];
        sum0 += fmaxf(acc[nt][0] + b10, 0.f) * w0 +
                fmaxf(acc[nt][1] + b11, 0.f) * w1;
        sum1 += fmaxf(acc[nt][2] + b10, 0.f) * w0 +
                fmaxf(acc[nt][3] + b11, 0.f) * w1;
    }
    sum0 += __shfl_xor_sync(0xffffffffu, sum0, 1);
    sum0 += __shfl_xor_sync(0xffffffffu, sum0, 2);
    sum1 += __shfl_xor_sync(0xffffffffu, sum1, 1);
    sum1 += __shfl_xor_sync(0xffffffffu, sum1, 2);
    if (tg == 0) {
        s_lk[wn][m0 + g]     = sum0;
        s_lk[wn][m0 + g + 8] = sum1;
    }
    __syncthreads();

    if (tid < 64) {
        int t = t0 + tid;
        if (t < TT) {
            float lk = s_lk[0][tid] + s_lk[1][tid] + blk[0];
            float err = KCOEF * g_C * sqrtf(s_n2[tid]) + TINY;
            g_lk[t] = lk;
            g_elk[t] = err;
            atomicMax(&g_segscr[s_src[tid]], fenc(lk - err));
        }
    }
}

// ------------------------- candidate compaction -----------------------------
__global__ void k_compact(const int* __restrict__ esrc) {
    int t = blockIdx.x * blockDim.x + threadIdx.x;
    if (t >= TT) return;
    int s = (t < NE) ? esrc[t] : (t - NE);
    if (fenc(g_lk[t] + g_elk[t]) >= g_segscr[s]) {
        int slot = atomicAdd(&g_ncand, 1);
        g_cand[slot] = t;
        g_slot[t] = slot;
    }
}

// ------------------------- exact fp32 rescore of candidates -----------------
__global__ __launch_bounds__(256) void k_rescore(
    const float* __restrict__ W1, const float* __restrict__ b1,
    const float* __restrict__ Wlk, const float* __restrict__ blk,
    const int* __restrict__ esrc, const int* __restrict__ edst)
{
    const int c0 = blockIdx.x * 64;
    const int nc = g_ncand;
    if (c0 >= nc) return;

    __shared__ float Zs[32][68];
    __shared__ float Bs[32 * 256];
    __shared__ int s_src[64], s_dst[64], s_t[64];

    const int tid = threadIdx.x;
    const int cg = tid & 31, eg = tid >> 5;

    if (tid < 64) {
        int c = c0 + tid;
        int s = -1, d = -1, t = -1;
        if (c < nc) {
            t = g_cand[c];
            if (t < NE) { s = esrc[t]; d = edst[t]; }
            else        { s = t - NE; }
        }
        s_src[tid] = s; s_dst[tid] = d; s_t[tid] = t;
    }
    __syncthreads();

    float acc[8][8];
    #pragma unroll
    for (int i = 0; i < 8; i++)
        #pragma unroll
        for (int j = 0; j < 8; j++) acc[i][j] = 0.f;

    for (int k0 = 0; k0 < H0D; k0 += 32) {
        #pragma unroll
        for (int l = 0; l < 8; l++) {
            int idx = tid + l * 256;
            int e = idx >> 5, kk = idx & 31;
            int s = s_src[e];
            float v = 0.f;
            if (s >= 0) {
                v = g_A[(size_t)s * H0D + k0 + kk];
                int d = s_dst[e];
                if (d >= 0) v += g_B[(size_t)d * H0D + k0 + kk];
                v = fmaxf(v, 0.f);
            }
            Zs[kk][e] = v;
        }
        #pragma unroll
        for (int l = 0; l < 8; l++) {
            int idx4 = tid + l * 256;
            int kk = idx4 >> 6, c = (idx4 << 2) & 255;
            *(float4*)&Bs[kk * 256 + c] =
                *(const float4*)&W1[(size_t)(k0 + kk) * H1D + c];
        }
        __syncthreads();
        #pragma unroll
        for (int kk = 0; kk < 32; kk++) {
            float a[8], b[8];
            *(float4*)(a)     = *(const float4*)&Zs[kk][eg * 8];
            *(float4*)(a + 4) = *(const float4*)&Zs[kk][eg * 8 + 4];
            *(float4*)(b)     = *(const float4*)&Bs[kk * 256 + cg * 8];
            *(float4*)(b + 4) = *(const float4*)&Bs[kk * 256 + cg * 8 + 4];
            #pragma unroll
            for (int i = 0; i < 8; i++)
                #pragma unroll
                for (int j = 0; j < 8; j++)
                    acc[i][j] = fmaf(a[i], b[j], acc[i][j]);
        }
        __syncthreads();
    }

    float bb[8], wl[8];
    #pragma unroll
    for (int j = 0; j < 8; j++) {
        bb[j] = b1[cg * 8 + j];
        wl[j] = Wlk[cg * 8 + j];
    }

    float lkp[8];
    #pragma unroll
    for (int i = 0; i < 8; i++) {
        int e = eg * 8 + i;
        int c = c0 + e;
        float h[8];
        float p = 0.f;
        #pragma unroll
        for (int j = 0; j < 8; j++) {
            h[j] = fmaxf(acc[i][j] + bb[j], 0.f);
            p = fmaf(h[j], wl[j], p);
        }
        if (s_t[e] >= 0) {
            *(float4*)&g_h_cand[(size_t)c * H1D + cg * 8]     = *(float4*)h;
            *(float4*)&g_h_cand[(size_t)c * H1D + cg * 8 + 4] = *(float4*)(h + 4);
        }
        #pragma unroll
        for (int off = 16; off; off >>= 1)
            p += __shfl_xor_sync(0xffffffffu, p, off);
        lkp[i] = p;
    }

    if (cg == 0) {
        float lb = blk[0];
        #pragma unroll
        for (int i = 0; i < 8; i++) {
            int e = eg * 8 + i;
            int t = s_t[e];
            if (t >= 0) {
                float lk = lkp[i] + lb;
                unsigned long long key =
                    ((unsigned long long)fenc(lk) << 32) | (unsigned int)t;
                atomicMax(&g_seg2[s_src[e]], key);
            }
        }
    }
}

// ------------------------- winner decode + action head ----------------------
__global__ void k_final(const float* __restrict__ Wa, const float* __restrict__ ba,
                        const int* __restrict__ edst)
{
    int warp = (blockIdx.x * blockDim.x + threadIdx.x) >> 5;
    int lane = threadIdx.x & 31;
    if (warp >= NN) return;
    unsigned long long key = g_seg2[warp];
    int win = (int)(unsigned int)(key & 0xffffffffull);
    int chosen = (win < NE) ? edst[win] : -1;

    const float* h = &g_h_cand[(size_t)g_slot[win] * H1D];
    float s0 = 0.f, s1 = 0.f;
    #pragma unroll
    for (int j = 0; j < 8; j++) {
        float hv = h[lane + j * 32];
        s0 = fmaf(hv, Wa[(lane + j * 32) * 2 + 0], s0);
        s1 = fmaf(hv, Wa[(lane + j * 32) * 2 + 1], s1);
    }
    #pragma unroll
    for (int off = 16; off; off >>= 1) {
        s0 += __shfl_xor_sync(0xffffffffu, s0, off);
        s1 += __shfl_xor_sync(0xffffffffu, s1, off);
    }
    if (lane == 0) {
        float l0 = s0 + ba[0], l1 = s1 + ba[1];
        if (chosen >= 0 && (l1 > l0))
            atomicMax(&g_owner[chosen], warp);
    }
}

// ------------------------- recompute updated rows ---------------------------
__global__ __launch_bounds__(256) void k_newval(
    const float* __restrict__ feature, const float* __restrict__ We,
    const float* __restrict__ be, float* __restrict__ out)
{
    int t = blockIdx.x;
    int i = g_owner[t];
    if (i < 0) return;
    __shared__ float mf[FIN];
    int tid = threadIdx.x;
    for (int k = tid; k < FIN; k += 256)
        mf[k] = 0.5f * (feature[(size_t)i * FIN + k] + feature[(size_t)t * FIN + k]);
    __syncthreads();
    float acc = 0.f;
    #pragma unroll 8
    for (int k = 0; k < FIN; k++)
        acc = fmaf(mf[k], We[(size_t)k * ED + tid], acc);
    out[(size_t)t * ED + tid] = fmaxf(acc + be[tid], 0.f);
}

// ---------------------------------------------------------------------------
extern "C" void kernel_launch(void* const* d_in, const int* in_sizes, int n_in,
                              void* d_out, int out_size) {
    const float* feature = (const float*)d_in[0];
    const float* We      = (const float*)d_in[1];
    const float* be      = (const float*)d_in[2];
    const float* W0      = (const float*)d_in[3];
    const float* b0      = (const float*)d_in[4];
    const float* W1      = (const float*)d_in[5];
    const float* b1      = (const float*)d_in[6];
    const float* Wlk     = (const float*)d_in[7];
    const float* blk     = (const float*)d_in[8];
    const float* Wa      = (const float*)d_in[9];
    const float* ba      = (const float*)d_in[10];
    const int*   esrc    = (const int*)d_in[11];
    const int*   edst    = (const int*)d_in[12];
    float* out = (float*)d_out;

    static int smem_set = 0;
    if (!smem_set) {
        cudaFuncSetAttribute(k_screen,
                             cudaFuncAttributeMaxDynamicSharedMemorySize,
                             HMMA_SMEM);
        cudaFuncSetAttribute(k_hgemm,
                             cudaFuncAttributeMaxDynamicSharedMemorySize,
                             HMMA_SMEM);
        smem_set = 1;
    }

    k_init<<<(NN + 255) / 256, 256>>>();
    k_prepw<<<(H0D * H0D + 255) / 256, 256>>>(W1, We, W0);
    k_prepc<<<1, 256>>>(W1, Wlk);

    k_hgemm<<<dim3(157, 1, 1), 256, HMMA_SMEM>>>(
        feature, FIN, NN, 16, 0, 0, be, out, 0, ED, 1);
    k_hgemm<<<dim3(157, 2, 2), 256, HMMA_SMEM>>>(
        out, ED, NN, 8, 1, 1, b0, nullptr, 1, H0D, 0);

    k_screen<<<(TT + 63) / 64, 256, HMMA_SMEM>>>(b1, Wlk, blk, esrc, edst);
    k_compact<<<(TT + 255) / 256, 256>>>(esrc);
    k_rescore<<<(TT + 63) / 64, 256>>>(W1, b1, Wlk, blk, esrc, edst);
    k_final<<<(NN * 32 + 255) / 256, 256>>>(Wa, ba, edst);
    k_newval<<<NN, 256>>>(feature, We, be, out);
}